// round 1
// baseline (speedup 1.0000x reference)
#include <cuda_runtime.h>
#include <math.h>
#include <stdint.h>

// Problem constants
#define B_DIM 2
#define T_DIM 2048
#define C_DIM 768
#define H_DIM 12
#define D_DIM 64
#define M_ROWS (B_DIM * T_DIM)      // 4096
#define DFF (4 * C_DIM)             // 3072
#define QKV_N (3 * C_DIM)           // 2304

// ---------------------------------------------------------------------------
// Scratch (device globals: no allocation allowed in kernel_launch)
// ---------------------------------------------------------------------------
__device__ float g_qkv [M_ROWS * QKV_N];   // (B*T, 3C)
__device__ float g_attn[M_ROWS * C_DIM];   // attention output, (B,T,C) layout
__device__ float g_proj[M_ROWS * C_DIM];   // attn @ Wp + bp
__device__ float g_out1[M_ROWS * C_DIM];   // x + LN(proj)
__device__ float g_hid [M_ROWS * DFF];     // gelu(out1 @ W1 + b1)
__device__ float g_mlp [M_ROWS * C_DIM];   // hid @ W2 + b2

// ---------------------------------------------------------------------------
// Generic tiled fp32 GEMM: C = A(MxK) @ W(KxN) + bias, optional exact GELU.
// 64x64 tile, BK=16, 256 threads, 4x4 register tile per thread.
// ---------------------------------------------------------------------------
template <bool GELU>
__global__ void gemm_bias_kernel(const float* __restrict__ A,
                                 const float* __restrict__ W,
                                 const float* __restrict__ bias,
                                 float* __restrict__ Cout,
                                 int M, int N, int K) {
    __shared__ float As[64][17];   // [m][k], padded
    __shared__ float Ws[16][65];   // [k][n], padded

    const int tid = threadIdx.x;
    const int tx = tid & 15;       // column group
    const int ty = tid >> 4;       // row group
    const int bm = blockIdx.y * 64;
    const int bn = blockIdx.x * 64;

    float acc[4][4] = {};

    for (int k0 = 0; k0 < K; k0 += 16) {
        // Load A tile 64x16
        #pragma unroll
        for (int idx = tid; idx < 64 * 16; idx += 256) {
            int m = idx >> 4, k = idx & 15;
            As[m][k] = A[(size_t)(bm + m) * K + k0 + k];
        }
        // Load W tile 16x64
        #pragma unroll
        for (int idx = tid; idx < 16 * 64; idx += 256) {
            int k = idx >> 6, n = idx & 63;
            Ws[k][n] = W[(size_t)(k0 + k) * N + bn + n];
        }
        __syncthreads();

        #pragma unroll
        for (int k = 0; k < 16; k++) {
            float a[4], b[4];
            #pragma unroll
            for (int i = 0; i < 4; i++) a[i] = As[ty * 4 + i][k];
            #pragma unroll
            for (int j = 0; j < 4; j++) b[j] = Ws[k][tx * 4 + j];
            #pragma unroll
            for (int i = 0; i < 4; i++)
                #pragma unroll
                for (int j = 0; j < 4; j++)
                    acc[i][j] = fmaf(a[i], b[j], acc[i][j]);
        }
        __syncthreads();
    }

    #pragma unroll
    for (int i = 0; i < 4; i++) {
        int m = bm + ty * 4 + i;
        #pragma unroll
        for (int j = 0; j < 4; j++) {
            int n = bn + tx * 4 + j;
            float v = acc[i][j] + bias[n];
            if (GELU) {
                v = 0.5f * v * (1.0f + erff(v * 0.70710678118654752f));
            }
            Cout[(size_t)m * N + n] = v;
        }
    }
}

// ---------------------------------------------------------------------------
// Flash-style attention (fp32, online softmax).
// Grid: (T/64, B*H). Block: 256 threads (16x16 layout, 4x4 per thread).
// Dynamic smem: Qs, Ks, Vs, Ps  each 64 x 65 floats.
// ---------------------------------------------------------------------------
#define ATTN_PAD 65
#define ATTN_SMEM_BYTES (4 * 64 * ATTN_PAD * 4)

__global__ void attn_kernel(const int* __restrict__ mask,
                            float* __restrict__ attn_out) {
    extern __shared__ float smem[];
    float* Qs = smem;                       // [64][65]
    float* Ks = Qs + 64 * ATTN_PAD;
    float* Vs = Ks + 64 * ATTN_PAD;
    float* Ps = Vs + 64 * ATTN_PAD;

    const int tid = threadIdx.x;
    const int tx = tid & 15;
    const int ty = tid >> 4;
    const int r0 = ty * 4;    // rows owned (scores & output)
    const int c0 = tx * 4;    // score cols / output d-cols owned

    const int bh = blockIdx.y;
    const int b = bh / H_DIM;
    const int h = bh % H_DIM;
    const int qt0 = blockIdx.x * 64;       // first query row in this tile

    const float scale = 0.125f;            // 1/sqrt(64)

    // Load Q tile: Qs[r][d] = qkv[(b*T + qt0 + r)*2304 + h*64 + d]
    for (int idx = tid; idx < 64 * 64; idx += 256) {
        int r = idx >> 6, d = idx & 63;
        Qs[r * ATTN_PAD + d] =
            g_qkv[(size_t)(b * T_DIM + qt0 + r) * QKV_N + h * D_DIM + d];
    }

    float m_i[4], l_i[4], o[4][4];
    #pragma unroll
    for (int i = 0; i < 4; i++) {
        m_i[i] = -INFINITY;
        l_i[i] = 0.0f;
        #pragma unroll
        for (int j = 0; j < 4; j++) o[i][j] = 0.0f;
    }

    for (int kt0 = 0; kt0 < T_DIM; kt0 += 64) {
        __syncthreads();  // protect Ks/Vs/Ps from previous iteration readers
        // Load K, V tiles
        for (int idx = tid; idx < 64 * 64; idx += 256) {
            int c = idx >> 6, d = idx & 63;
            size_t base = (size_t)(b * T_DIM + kt0 + c) * QKV_N + h * D_DIM + d;
            Ks[c * ATTN_PAD + d] = g_qkv[base + C_DIM];
            Vs[c * ATTN_PAD + d] = g_qkv[base + 2 * C_DIM];
        }
        __syncthreads();

        // S = Q @ K^T for this thread's 4x4
        float s[4][4] = {};
        #pragma unroll
        for (int d = 0; d < 64; d++) {
            float q[4], k[4];
            #pragma unroll
            for (int i = 0; i < 4; i++) q[i] = Qs[(r0 + i) * ATTN_PAD + d];
            #pragma unroll
            for (int j = 0; j < 4; j++) k[j] = Ks[(c0 + j) * ATTN_PAD + d];
            #pragma unroll
            for (int i = 0; i < 4; i++)
                #pragma unroll
                for (int j = 0; j < 4; j++)
                    s[i][j] = fmaf(q[i], k[j], s[i][j]);
        }
        // scale + mask
        int mk[4];
        #pragma unroll
        for (int j = 0; j < 4; j++) mk[j] = mask[b * T_DIM + kt0 + c0 + j];
        #pragma unroll
        for (int i = 0; i < 4; i++)
            #pragma unroll
            for (int j = 0; j < 4; j++)
                s[i][j] = (mk[j] == 0) ? -1e30f : s[i][j] * scale;

        // Online softmax: per-row (16 lanes per row group, contiguous) reduce
        float alpha[4];
        #pragma unroll
        for (int i = 0; i < 4; i++) {
            float vmax = fmaxf(fmaxf(s[i][0], s[i][1]), fmaxf(s[i][2], s[i][3]));
            #pragma unroll
            for (int off = 8; off >= 1; off >>= 1)
                vmax = fmaxf(vmax, __shfl_xor_sync(0xffffffffu, vmax, off));
            float m_new = fmaxf(m_i[i], vmax);
            alpha[i] = expf(m_i[i] - m_new);
            float rowsum = 0.0f;
            #pragma unroll
            for (int j = 0; j < 4; j++) {
                s[i][j] = expf(s[i][j] - m_new);
                rowsum += s[i][j];
            }
            #pragma unroll
            for (int off = 8; off >= 1; off >>= 1)
                rowsum += __shfl_xor_sync(0xffffffffu, rowsum, off);
            l_i[i] = l_i[i] * alpha[i] + rowsum;
            m_i[i] = m_new;
            #pragma unroll
            for (int j = 0; j < 4; j++) o[i][j] *= alpha[i];
        }

        // Store P, then O += P @ V
        #pragma unroll
        for (int i = 0; i < 4; i++)
            #pragma unroll
            for (int j = 0; j < 4; j++)
                Ps[(r0 + i) * ATTN_PAD + c0 + j] = s[i][j];
        __syncthreads();

        #pragma unroll
        for (int c = 0; c < 64; c++) {
            float p[4], v[4];
            #pragma unroll
            for (int i = 0; i < 4; i++) p[i] = Ps[(r0 + i) * ATTN_PAD + c];
            #pragma unroll
            for (int j = 0; j < 4; j++) v[j] = Vs[c * ATTN_PAD + c0 + j];
            #pragma unroll
            for (int i = 0; i < 4; i++)
                #pragma unroll
                for (int j = 0; j < 4; j++)
                    o[i][j] = fmaf(p[i], v[j], o[i][j]);
        }
    }

    // Write output: (B,T,H*D)
    #pragma unroll
    for (int i = 0; i < 4; i++) {
        float inv_l = 1.0f / l_i[i];
        int t = qt0 + r0 + i;
        #pragma unroll
        for (int j = 0; j < 4; j++) {
            attn_out[(size_t)(b * T_DIM + t) * C_DIM + h * D_DIM + c0 + j] =
                o[i][j] * inv_l;
        }
    }
}

// ---------------------------------------------------------------------------
// Fused LayerNorm + residual: out = res + LN(a) * gamma + beta
// One block per row (C=768), 256 threads.
// ---------------------------------------------------------------------------
__global__ void ln_residual_kernel(const float* __restrict__ res,
                                   const float* __restrict__ a,
                                   const float* __restrict__ gamma,
                                   const float* __restrict__ beta,
                                   float* __restrict__ out) {
    const int row = blockIdx.x;
    const float* ar = a + (size_t)row * C_DIM;
    const float* rr = res + (size_t)row * C_DIM;
    float* outr = out + (size_t)row * C_DIM;

    float s = 0.0f, s2 = 0.0f;
    float v[3];
    #pragma unroll
    for (int k = 0; k < 3; k++) {
        v[k] = ar[threadIdx.x + k * 256];
        s += v[k];
        s2 += v[k] * v[k];
    }
    // warp reduce
    #pragma unroll
    for (int off = 16; off >= 1; off >>= 1) {
        s  += __shfl_xor_sync(0xffffffffu, s, off);
        s2 += __shfl_xor_sync(0xffffffffu, s2, off);
    }
    __shared__ float red_s[8], red_s2[8];
    int warp = threadIdx.x >> 5, lane = threadIdx.x & 31;
    if (lane == 0) { red_s[warp] = s; red_s2[warp] = s2; }
    __syncthreads();
    if (warp == 0) {
        s  = (lane < 8) ? red_s[lane]  : 0.0f;
        s2 = (lane < 8) ? red_s2[lane] : 0.0f;
        #pragma unroll
        for (int off = 4; off >= 1; off >>= 1) {
            s  += __shfl_xor_sync(0xffffffffu, s, off);
            s2 += __shfl_xor_sync(0xffffffffu, s2, off);
        }
        if (lane == 0) { red_s[0] = s; red_s2[0] = s2; }
    }
    __syncthreads();
    const float mean = red_s[0] * (1.0f / C_DIM);
    const float var  = red_s2[0] * (1.0f / C_DIM) - mean * mean;
    const float rstd = rsqrtf(var + 1e-5f);

    #pragma unroll
    for (int k = 0; k < 3; k++) {
        int i = threadIdx.x + k * 256;
        outr[i] = rr[i] + (v[k] - mean) * rstd * gamma[i] + beta[i];
    }
}

// ---------------------------------------------------------------------------
// Launch
// ---------------------------------------------------------------------------
extern "C" void kernel_launch(void* const* d_in, const int* in_sizes, int n_in,
                              void* d_out, int out_size) {
    const float* x    = (const float*)d_in[0];
    const int*   mask = (const int*)  d_in[1];
    const float* Wqkv = (const float*)d_in[2];
    const float* bqkv = (const float*)d_in[3];
    const float* Wp   = (const float*)d_in[4];
    const float* bp   = (const float*)d_in[5];
    const float* g1   = (const float*)d_in[6];
    const float* be1  = (const float*)d_in[7];
    const float* W1   = (const float*)d_in[8];
    const float* b1   = (const float*)d_in[9];
    const float* W2   = (const float*)d_in[10];
    const float* b2   = (const float*)d_in[11];
    const float* g2   = (const float*)d_in[12];
    const float* be2  = (const float*)d_in[13];
    float* out = (float*)d_out;

    // Scratch pointers
    float *qkv, *attn, *proj, *out1, *hid, *mlp;
    cudaGetSymbolAddress((void**)&qkv,  g_qkv);
    cudaGetSymbolAddress((void**)&attn, g_attn);
    cudaGetSymbolAddress((void**)&proj, g_proj);
    cudaGetSymbolAddress((void**)&out1, g_out1);
    cudaGetSymbolAddress((void**)&hid,  g_hid);
    cudaGetSymbolAddress((void**)&mlp,  g_mlp);

    cudaFuncSetAttribute(attn_kernel,
                         cudaFuncAttributeMaxDynamicSharedMemorySize,
                         ATTN_SMEM_BYTES);

    dim3 blk(256);

    // 1) QKV projection: (4096 x 768) @ (768 x 2304)
    gemm_bias_kernel<false><<<dim3(QKV_N / 64, M_ROWS / 64), blk>>>(
        x, Wqkv, bqkv, qkv, M_ROWS, QKV_N, C_DIM);

    // 2) Attention
    attn_kernel<<<dim3(T_DIM / 64, B_DIM * H_DIM), blk, ATTN_SMEM_BYTES>>>(
        mask, attn);

    // 3) Output projection: (4096 x 768) @ (768 x 768)
    gemm_bias_kernel<false><<<dim3(C_DIM / 64, M_ROWS / 64), blk>>>(
        attn, Wp, bp, proj, M_ROWS, C_DIM, C_DIM);

    // 4) out1 = x + LN(proj)
    ln_residual_kernel<<<M_ROWS, blk>>>(x, proj, g1, be1, out1);

    // 5) hid = gelu(out1 @ W1 + b1): (4096 x 3072)
    gemm_bias_kernel<true><<<dim3(DFF / 64, M_ROWS / 64), blk>>>(
        out1, W1, b1, hid, M_ROWS, DFF, C_DIM);

    // 6) mlp = hid @ W2 + b2: (4096 x 768), K=3072
    gemm_bias_kernel<false><<<dim3(C_DIM / 64, M_ROWS / 64), blk>>>(
        hid, W2, b2, mlp, M_ROWS, C_DIM, DFF);

    // 7) out = out1 + LN(mlp)
    ln_residual_kernel<<<M_ROWS, blk>>>(out1, mlp, g2, be2, out);
}

// round 2
// speedup vs baseline: 2.5241x; 2.5241x over previous
#include <cuda_runtime.h>
#include <math.h>
#include <stdint.h>

// Problem constants
#define B_DIM 2
#define T_DIM 2048
#define C_DIM 768
#define H_DIM 12
#define D_DIM 64
#define M_ROWS (B_DIM * T_DIM)      // 4096
#define DFF (4 * C_DIM)             // 3072
#define QKV_N (3 * C_DIM)           // 2304

// ---------------------------------------------------------------------------
// Scratch (device globals: no allocation allowed in kernel_launch)
// ---------------------------------------------------------------------------
__device__ float g_qkv [M_ROWS * QKV_N];   // (B*T, 3C)
__device__ float g_attn[M_ROWS * C_DIM];   // attention output, (B,T,C) layout
__device__ float g_proj[M_ROWS * C_DIM];   // attn @ Wp + bp
__device__ float g_out1[M_ROWS * C_DIM];   // x + LN(proj)
__device__ float g_hid [M_ROWS * DFF];     // gelu(out1 @ W1 + b1)
__device__ float g_mlp [M_ROWS * C_DIM];   // hid @ W2 + b2

__device__ __forceinline__ uint32_t f2tf32(float f) {
    uint32_t r;
    asm("cvt.rna.tf32.f32 %0, %1;" : "=r"(r) : "f"(f));
    return r;
}

__device__ __forceinline__ void mma_tf32(float& d0, float& d1, float& d2, float& d3,
                                         uint32_t a0, uint32_t a1, uint32_t a2, uint32_t a3,
                                         uint32_t b0, uint32_t b1) {
    asm volatile(
        "mma.sync.aligned.m16n8k8.row.col.f32.tf32.tf32.f32 "
        "{%0,%1,%2,%3}, {%4,%5,%6,%7}, {%8,%9}, {%0,%1,%2,%3};\n"
        : "+f"(d0), "+f"(d1), "+f"(d2), "+f"(d3)
        : "r"(a0), "r"(a1), "r"(a2), "r"(a3), "r"(b0), "r"(b1));
}

// ---------------------------------------------------------------------------
// tf32 tensor-core GEMM: C = A(MxK) @ W(KxN) + bias, optional exact GELU.
// CTA tile 128x128, BK=32, 256 threads (8 warps, 2x4 grid; warp tile 64x32).
// Requires M%128==0, N%128==0, K%32==0.
// ---------------------------------------------------------------------------
#define GBM 128
#define GBN 128
#define GBK 32
#define A_PITCH 36
#define B_PITCH 136

template <bool GELU>
__global__ void __launch_bounds__(256, 2)
gemm_tf32_kernel(const float* __restrict__ A,
                 const float* __restrict__ W,
                 const float* __restrict__ bias,
                 float* __restrict__ Cout,
                 int M, int N, int K) {
    __shared__ uint32_t As[GBM][A_PITCH];   // [m][k], pitch 36 -> conflict-free
    __shared__ uint32_t Bs[GBK][B_PITCH];   // [k][n], pitch 136 -> conflict-free

    const int tid = threadIdx.x;
    const int lane = tid & 31;
    const int w = tid >> 5;
    const int warp_m = (w & 1) * 64;       // 2 warp rows
    const int warp_n = (w >> 1) * 32;      // 4 warp cols
    const int bm = blockIdx.y * GBM;
    const int bn = blockIdx.x * GBN;

    const int grp = lane >> 2;             // 0..7
    const int thr = lane & 3;              // 0..3

    float acc[4][4][4];                    // [mt][nt][reg]
    #pragma unroll
    for (int mt = 0; mt < 4; mt++)
        #pragma unroll
        for (int nt = 0; nt < 4; nt++)
            #pragma unroll
            for (int r = 0; r < 4; r++) acc[mt][nt][r] = 0.0f;

    for (int k0 = 0; k0 < K; k0 += GBK) {
        // Load A tile 128x32 (float4 each), convert to tf32
        #pragma unroll
        for (int i = 0; i < 4; i++) {
            int idx = tid + i * 256;            // 0..1023 float4s
            int r = idx >> 3;                   // 8 float4 per row
            int c4 = idx & 7;
            float4 v = *(const float4*)&A[(size_t)(bm + r) * K + k0 + c4 * 4];
            As[r][c4 * 4 + 0] = f2tf32(v.x);
            As[r][c4 * 4 + 1] = f2tf32(v.y);
            As[r][c4 * 4 + 2] = f2tf32(v.z);
            As[r][c4 * 4 + 3] = f2tf32(v.w);
        }
        // Load B tile 32x128
        #pragma unroll
        for (int i = 0; i < 4; i++) {
            int idx = tid + i * 256;
            int r = idx >> 5;                   // 32 float4 per row
            int c4 = idx & 31;
            float4 v = *(const float4*)&W[(size_t)(k0 + r) * N + bn + c4 * 4];
            Bs[r][c4 * 4 + 0] = f2tf32(v.x);
            Bs[r][c4 * 4 + 1] = f2tf32(v.y);
            Bs[r][c4 * 4 + 2] = f2tf32(v.z);
            Bs[r][c4 * 4 + 3] = f2tf32(v.w);
        }
        __syncthreads();

        #pragma unroll
        for (int kk = 0; kk < GBK; kk += 8) {
            uint32_t af[4][4], bf[4][2];
            #pragma unroll
            for (int mt = 0; mt < 4; mt++) {
                int r = warp_m + mt * 16 + grp;
                af[mt][0] = As[r][kk + thr];
                af[mt][1] = As[r + 8][kk + thr];
                af[mt][2] = As[r][kk + thr + 4];
                af[mt][3] = As[r + 8][kk + thr + 4];
            }
            #pragma unroll
            for (int nt = 0; nt < 4; nt++) {
                int c = warp_n + nt * 8 + grp;
                bf[nt][0] = Bs[kk + thr][c];
                bf[nt][1] = Bs[kk + thr + 4][c];
            }
            #pragma unroll
            for (int mt = 0; mt < 4; mt++)
                #pragma unroll
                for (int nt = 0; nt < 4; nt++)
                    mma_tf32(acc[mt][nt][0], acc[mt][nt][1],
                             acc[mt][nt][2], acc[mt][nt][3],
                             af[mt][0], af[mt][1], af[mt][2], af[mt][3],
                             bf[nt][0], bf[nt][1]);
        }
        __syncthreads();
    }

    // Epilogue: D layout — d0,d1 at [row][col], [row][col+1]; d2,d3 at row+8.
    #pragma unroll
    for (int mt = 0; mt < 4; mt++) {
        #pragma unroll
        for (int nt = 0; nt < 4; nt++) {
            int m0 = bm + warp_m + mt * 16 + grp;
            int n0 = bn + warp_n + nt * 8 + thr * 2;
            float bx = bias[n0], by = bias[n0 + 1];
            float v0 = acc[mt][nt][0] + bx;
            float v1 = acc[mt][nt][1] + by;
            float v2 = acc[mt][nt][2] + bx;
            float v3 = acc[mt][nt][3] + by;
            if (GELU) {
                v0 = 0.5f * v0 * (1.0f + erff(v0 * 0.70710678118654752f));
                v1 = 0.5f * v1 * (1.0f + erff(v1 * 0.70710678118654752f));
                v2 = 0.5f * v2 * (1.0f + erff(v2 * 0.70710678118654752f));
                v3 = 0.5f * v3 * (1.0f + erff(v3 * 0.70710678118654752f));
            }
            *(float2*)&Cout[(size_t)m0 * N + n0] = make_float2(v0, v1);
            *(float2*)&Cout[(size_t)(m0 + 8) * N + n0] = make_float2(v2, v3);
        }
    }
}

// ---------------------------------------------------------------------------
// Flash-style attention (fp32, online softmax).
// Grid: (T/64, B*H). Block: 256 threads (16x16 layout, 4x4 per thread).
// ---------------------------------------------------------------------------
#define ATTN_PAD 65
#define ATTN_SMEM_BYTES (4 * 64 * ATTN_PAD * 4)

__global__ void attn_kernel(const int* __restrict__ mask,
                            float* __restrict__ attn_out) {
    extern __shared__ float smem[];
    float* Qs = smem;                       // [64][65]
    float* Ks = Qs + 64 * ATTN_PAD;
    float* Vs = Ks + 64 * ATTN_PAD;
    float* Ps = Vs + 64 * ATTN_PAD;

    const int tid = threadIdx.x;
    const int tx = tid & 15;
    const int ty = tid >> 4;
    const int r0 = ty * 4;
    const int c0 = tx * 4;

    const int bh = blockIdx.y;
    const int b = bh / H_DIM;
    const int h = bh % H_DIM;
    const int qt0 = blockIdx.x * 64;

    const float scale = 0.125f;            // 1/sqrt(64)

    for (int idx = tid; idx < 64 * 64; idx += 256) {
        int r = idx >> 6, d = idx & 63;
        Qs[r * ATTN_PAD + d] =
            g_qkv[(size_t)(b * T_DIM + qt0 + r) * QKV_N + h * D_DIM + d];
    }

    float m_i[4], l_i[4], o[4][4];
    #pragma unroll
    for (int i = 0; i < 4; i++) {
        m_i[i] = -INFINITY;
        l_i[i] = 0.0f;
        #pragma unroll
        for (int j = 0; j < 4; j++) o[i][j] = 0.0f;
    }

    for (int kt0 = 0; kt0 < T_DIM; kt0 += 64) {
        __syncthreads();
        for (int idx = tid; idx < 64 * 64; idx += 256) {
            int c = idx >> 6, d = idx & 63;
            size_t base = (size_t)(b * T_DIM + kt0 + c) * QKV_N + h * D_DIM + d;
            Ks[c * ATTN_PAD + d] = g_qkv[base + C_DIM];
            Vs[c * ATTN_PAD + d] = g_qkv[base + 2 * C_DIM];
        }
        __syncthreads();

        float s[4][4] = {};
        #pragma unroll
        for (int d = 0; d < 64; d++) {
            float q[4], k[4];
            #pragma unroll
            for (int i = 0; i < 4; i++) q[i] = Qs[(r0 + i) * ATTN_PAD + d];
            #pragma unroll
            for (int j = 0; j < 4; j++) k[j] = Ks[(c0 + j) * ATTN_PAD + d];
            #pragma unroll
            for (int i = 0; i < 4; i++)
                #pragma unroll
                for (int j = 0; j < 4; j++)
                    s[i][j] = fmaf(q[i], k[j], s[i][j]);
        }
        int mk[4];
        #pragma unroll
        for (int j = 0; j < 4; j++) mk[j] = mask[b * T_DIM + kt0 + c0 + j];
        #pragma unroll
        for (int i = 0; i < 4; i++)
            #pragma unroll
            for (int j = 0; j < 4; j++)
                s[i][j] = (mk[j] == 0) ? -1e30f : s[i][j] * scale;

        float alpha[4];
        #pragma unroll
        for (int i = 0; i < 4; i++) {
            float vmax = fmaxf(fmaxf(s[i][0], s[i][1]), fmaxf(s[i][2], s[i][3]));
            #pragma unroll
            for (int off = 8; off >= 1; off >>= 1)
                vmax = fmaxf(vmax, __shfl_xor_sync(0xffffffffu, vmax, off));
            float m_new = fmaxf(m_i[i], vmax);
            alpha[i] = expf(m_i[i] - m_new);
            float rowsum = 0.0f;
            #pragma unroll
            for (int j = 0; j < 4; j++) {
                s[i][j] = expf(s[i][j] - m_new);
                rowsum += s[i][j];
            }
            #pragma unroll
            for (int off = 8; off >= 1; off >>= 1)
                rowsum += __shfl_xor_sync(0xffffffffu, rowsum, off);
            l_i[i] = l_i[i] * alpha[i] + rowsum;
            m_i[i] = m_new;
            #pragma unroll
            for (int j = 0; j < 4; j++) o[i][j] *= alpha[i];
        }

        #pragma unroll
        for (int i = 0; i < 4; i++)
            #pragma unroll
            for (int j = 0; j < 4; j++)
                Ps[(r0 + i) * ATTN_PAD + c0 + j] = s[i][j];
        __syncthreads();

        #pragma unroll
        for (int c = 0; c < 64; c++) {
            float p[4], v[4];
            #pragma unroll
            for (int i = 0; i < 4; i++) p[i] = Ps[(r0 + i) * ATTN_PAD + c];
            #pragma unroll
            for (int j = 0; j < 4; j++) v[j] = Vs[c * ATTN_PAD + c0 + j];
            #pragma unroll
            for (int i = 0; i < 4; i++)
                #pragma unroll
                for (int j = 0; j < 4; j++)
                    o[i][j] = fmaf(p[i], v[j], o[i][j]);
        }
    }

    #pragma unroll
    for (int i = 0; i < 4; i++) {
        float inv_l = 1.0f / l_i[i];
        int t = qt0 + r0 + i;
        #pragma unroll
        for (int j = 0; j < 4; j++) {
            attn_out[(size_t)(b * T_DIM + t) * C_DIM + h * D_DIM + c0 + j] =
                o[i][j] * inv_l;
        }
    }
}

// ---------------------------------------------------------------------------
// Fused LayerNorm + residual: out = res + LN(a) * gamma + beta
// ---------------------------------------------------------------------------
__global__ void ln_residual_kernel(const float* __restrict__ res,
                                   const float* __restrict__ a,
                                   const float* __restrict__ gamma,
                                   const float* __restrict__ beta,
                                   float* __restrict__ out) {
    const int row = blockIdx.x;
    const float* ar = a + (size_t)row * C_DIM;
    const float* rr = res + (size_t)row * C_DIM;
    float* outr = out + (size_t)row * C_DIM;

    float s = 0.0f, s2 = 0.0f;
    float v[3];
    #pragma unroll
    for (int k = 0; k < 3; k++) {
        v[k] = ar[threadIdx.x + k * 256];
        s += v[k];
        s2 += v[k] * v[k];
    }
    #pragma unroll
    for (int off = 16; off >= 1; off >>= 1) {
        s  += __shfl_xor_sync(0xffffffffu, s, off);
        s2 += __shfl_xor_sync(0xffffffffu, s2, off);
    }
    __shared__ float red_s[8], red_s2[8];
    int warp = threadIdx.x >> 5, lane = threadIdx.x & 31;
    if (lane == 0) { red_s[warp] = s; red_s2[warp] = s2; }
    __syncthreads();
    if (warp == 0) {
        s  = (lane < 8) ? red_s[lane]  : 0.0f;
        s2 = (lane < 8) ? red_s2[lane] : 0.0f;
        #pragma unroll
        for (int off = 4; off >= 1; off >>= 1) {
            s  += __shfl_xor_sync(0xffffffffu, s, off);
            s2 += __shfl_xor_sync(0xffffffffu, s2, off);
        }
        if (lane == 0) { red_s[0] = s; red_s2[0] = s2; }
    }
    __syncthreads();
    const float mean = red_s[0] * (1.0f / C_DIM);
    const float var  = red_s2[0] * (1.0f / C_DIM) - mean * mean;
    const float rstd = rsqrtf(var + 1e-5f);

    #pragma unroll
    for (int k = 0; k < 3; k++) {
        int i = threadIdx.x + k * 256;
        outr[i] = rr[i] + (v[k] - mean) * rstd * gamma[i] + beta[i];
    }
}

// ---------------------------------------------------------------------------
// Launch
// ---------------------------------------------------------------------------
extern "C" void kernel_launch(void* const* d_in, const int* in_sizes, int n_in,
                              void* d_out, int out_size) {
    const float* x    = (const float*)d_in[0];
    const int*   mask = (const int*)  d_in[1];
    const float* Wqkv = (const float*)d_in[2];
    const float* bqkv = (const float*)d_in[3];
    const float* Wp   = (const float*)d_in[4];
    const float* bp   = (const float*)d_in[5];
    const float* g1   = (const float*)d_in[6];
    const float* be1  = (const float*)d_in[7];
    const float* W1   = (const float*)d_in[8];
    const float* b1   = (const float*)d_in[9];
    const float* W2   = (const float*)d_in[10];
    const float* b2   = (const float*)d_in[11];
    const float* g2   = (const float*)d_in[12];
    const float* be2  = (const float*)d_in[13];
    float* out = (float*)d_out;

    float *qkv, *attn, *proj, *out1, *hid, *mlp;
    cudaGetSymbolAddress((void**)&qkv,  g_qkv);
    cudaGetSymbolAddress((void**)&attn, g_attn);
    cudaGetSymbolAddress((void**)&proj, g_proj);
    cudaGetSymbolAddress((void**)&out1, g_out1);
    cudaGetSymbolAddress((void**)&hid,  g_hid);
    cudaGetSymbolAddress((void**)&mlp,  g_mlp);

    cudaFuncSetAttribute(attn_kernel,
                         cudaFuncAttributeMaxDynamicSharedMemorySize,
                         ATTN_SMEM_BYTES);

    dim3 blk(256);

    // 1) QKV projection: (4096 x 2304) = (4096 x 768) @ (768 x 2304)
    gemm_tf32_kernel<false><<<dim3(QKV_N / GBN, M_ROWS / GBM), blk>>>(
        x, Wqkv, bqkv, qkv, M_ROWS, QKV_N, C_DIM);

    // 2) Attention
    attn_kernel<<<dim3(T_DIM / 64, B_DIM * H_DIM), blk, ATTN_SMEM_BYTES>>>(
        mask, attn);

    // 3) Output projection: (4096 x 768) @ (768 x 768)
    gemm_tf32_kernel<false><<<dim3(C_DIM / GBN, M_ROWS / GBM), blk>>>(
        attn, Wp, bp, proj, M_ROWS, C_DIM, C_DIM);

    // 4) out1 = x + LN(proj)
    ln_residual_kernel<<<M_ROWS, blk>>>(x, proj, g1, be1, out1);

    // 5) hid = gelu(out1 @ W1 + b1): (4096 x 3072)
    gemm_tf32_kernel<true><<<dim3(DFF / GBN, M_ROWS / GBM), blk>>>(
        out1, W1, b1, hid, M_ROWS, DFF, C_DIM);

    // 6) mlp = hid @ W2 + b2: (4096 x 768), K=3072
    gemm_tf32_kernel<false><<<dim3(C_DIM / GBN, M_ROWS / GBM), blk>>>(
        hid, W2, b2, mlp, M_ROWS, C_DIM, DFF);

    // 7) out = out1 + LN(mlp)
    ln_residual_kernel<<<M_ROWS, blk>>>(out1, mlp, g2, be2, out);
}

// round 3
// speedup vs baseline: 3.3956x; 1.3453x over previous
#include <cuda_runtime.h>
#include <math.h>
#include <stdint.h>

// Problem constants
#define B_DIM 2
#define T_DIM 2048
#define C_DIM 768
#define H_DIM 12
#define D_DIM 64
#define M_ROWS (B_DIM * T_DIM)      // 4096
#define DFF (4 * C_DIM)             // 3072
#define QKV_N (3 * C_DIM)           // 2304

// ---------------------------------------------------------------------------
// Scratch (device globals)
// ---------------------------------------------------------------------------
__device__ float g_qkv [M_ROWS * QKV_N];
__device__ float g_attn[M_ROWS * C_DIM];
__device__ float g_proj[M_ROWS * C_DIM];
__device__ float g_out1[M_ROWS * C_DIM];
__device__ float g_hid [M_ROWS * DFF];
__device__ float g_mlp [M_ROWS * C_DIM];

__device__ __forceinline__ uint32_t f2tf32(float f) {
    uint32_t r;
    asm("cvt.rna.tf32.f32 %0, %1;" : "=r"(r) : "f"(f));
    return r;
}

__device__ __forceinline__ void mma_tf32(float& d0, float& d1, float& d2, float& d3,
                                         uint32_t a0, uint32_t a1, uint32_t a2, uint32_t a3,
                                         uint32_t b0, uint32_t b1) {
    asm volatile(
        "mma.sync.aligned.m16n8k8.row.col.f32.tf32.tf32.f32 "
        "{%0,%1,%2,%3}, {%4,%5,%6,%7}, {%8,%9}, {%0,%1,%2,%3};\n"
        : "+f"(d0), "+f"(d1), "+f"(d2), "+f"(d3)
        : "r"(a0), "r"(a1), "r"(a2), "r"(a3), "r"(b0), "r"(b1));
}

// FMA-only exp (avoids the slow MUFU pipe). |rel err| ~2.4e-6 for x <= 0.
__device__ __forceinline__ float fast_exp(float x) {
    const float LOG2E = 1.4426950408889634f;
    float y = x * LOG2E;
    y = fmaxf(y, -125.0f);
    float t = y + 12582912.0f;            // round-to-nearest-int magic
    int j = __float_as_int(t);            // low bits hold (int)rint(y)
    float r = t - 12582912.0f;
    float f = y - r;                      // f in [-0.5, 0.5]
    float p = 1.333356e-3f;
    p = fmaf(p, f, 9.618129e-3f);
    p = fmaf(p, f, 5.550411e-2f);
    p = fmaf(p, f, 2.402265e-1f);
    p = fmaf(p, f, 6.931472e-1f);
    p = fmaf(p, f, 1.0f);
    return p * __int_as_float((j + 127) << 23);
}

// ---------------------------------------------------------------------------
// tf32 tensor-core GEMM (unchanged from R2): C = A @ W + bias, opt. exact GELU
// ---------------------------------------------------------------------------
#define GBM 128
#define GBN 128
#define GBK 32
#define A_PITCH 36
#define B_PITCH 136

template <bool GELU>
__global__ void __launch_bounds__(256, 2)
gemm_tf32_kernel(const float* __restrict__ A,
                 const float* __restrict__ W,
                 const float* __restrict__ bias,
                 float* __restrict__ Cout,
                 int M, int N, int K) {
    __shared__ uint32_t As[GBM][A_PITCH];
    __shared__ uint32_t Bs[GBK][B_PITCH];

    const int tid = threadIdx.x;
    const int lane = tid & 31;
    const int w = tid >> 5;
    const int warp_m = (w & 1) * 64;
    const int warp_n = (w >> 1) * 32;
    const int bm = blockIdx.y * GBM;
    const int bn = blockIdx.x * GBN;
    const int grp = lane >> 2;
    const int thr = lane & 3;

    float acc[4][4][4];
    #pragma unroll
    for (int mt = 0; mt < 4; mt++)
        #pragma unroll
        for (int nt = 0; nt < 4; nt++)
            #pragma unroll
            for (int r = 0; r < 4; r++) acc[mt][nt][r] = 0.0f;

    for (int k0 = 0; k0 < K; k0 += GBK) {
        #pragma unroll
        for (int i = 0; i < 4; i++) {
            int idx = tid + i * 256;
            int r = idx >> 3, c4 = idx & 7;
            float4 v = *(const float4*)&A[(size_t)(bm + r) * K + k0 + c4 * 4];
            As[r][c4 * 4 + 0] = f2tf32(v.x);
            As[r][c4 * 4 + 1] = f2tf32(v.y);
            As[r][c4 * 4 + 2] = f2tf32(v.z);
            As[r][c4 * 4 + 3] = f2tf32(v.w);
        }
        #pragma unroll
        for (int i = 0; i < 4; i++) {
            int idx = tid + i * 256;
            int r = idx >> 5, c4 = idx & 31;
            float4 v = *(const float4*)&W[(size_t)(k0 + r) * N + bn + c4 * 4];
            Bs[r][c4 * 4 + 0] = f2tf32(v.x);
            Bs[r][c4 * 4 + 1] = f2tf32(v.y);
            Bs[r][c4 * 4 + 2] = f2tf32(v.z);
            Bs[r][c4 * 4 + 3] = f2tf32(v.w);
        }
        __syncthreads();

        #pragma unroll
        for (int kk = 0; kk < GBK; kk += 8) {
            uint32_t af[4][4], bf[4][2];
            #pragma unroll
            for (int mt = 0; mt < 4; mt++) {
                int r = warp_m + mt * 16 + grp;
                af[mt][0] = As[r][kk + thr];
                af[mt][1] = As[r + 8][kk + thr];
                af[mt][2] = As[r][kk + thr + 4];
                af[mt][3] = As[r + 8][kk + thr + 4];
            }
            #pragma unroll
            for (int nt = 0; nt < 4; nt++) {
                int c = warp_n + nt * 8 + grp;
                bf[nt][0] = Bs[kk + thr][c];
                bf[nt][1] = Bs[kk + thr + 4][c];
            }
            #pragma unroll
            for (int mt = 0; mt < 4; mt++)
                #pragma unroll
                for (int nt = 0; nt < 4; nt++)
                    mma_tf32(acc[mt][nt][0], acc[mt][nt][1],
                             acc[mt][nt][2], acc[mt][nt][3],
                             af[mt][0], af[mt][1], af[mt][2], af[mt][3],
                             bf[nt][0], bf[nt][1]);
        }
        __syncthreads();
    }

    #pragma unroll
    for (int mt = 0; mt < 4; mt++) {
        #pragma unroll
        for (int nt = 0; nt < 4; nt++) {
            int m0 = bm + warp_m + mt * 16 + grp;
            int n0 = bn + warp_n + nt * 8 + thr * 2;
            float bx = bias[n0], by = bias[n0 + 1];
            float v0 = acc[mt][nt][0] + bx;
            float v1 = acc[mt][nt][1] + by;
            float v2 = acc[mt][nt][2] + bx;
            float v3 = acc[mt][nt][3] + by;
            if (GELU) {
                v0 = 0.5f * v0 * (1.0f + erff(v0 * 0.70710678118654752f));
                v1 = 0.5f * v1 * (1.0f + erff(v1 * 0.70710678118654752f));
                v2 = 0.5f * v2 * (1.0f + erff(v2 * 0.70710678118654752f));
                v3 = 0.5f * v3 * (1.0f + erff(v3 * 0.70710678118654752f));
            }
            *(float2*)&Cout[(size_t)m0 * N + n0] = make_float2(v0, v1);
            *(float2*)&Cout[(size_t)(m0 + 8) * N + n0] = make_float2(v2, v3);
        }
    }
}

// ---------------------------------------------------------------------------
// Tensor-core flash attention.
// Br=64 (4 warps x 16 rows), Bc=64. QK^T in split tf32 (3 mma, ~fp32 grade),
// P@V in single tf32. Softmax via FMA-only exp. Pitch-72 smem: conflict-free.
// ---------------------------------------------------------------------------
#define FA_PITCH 72
#define FA_QOFF   0
#define FA_SMEM_FLOATS (64*FA_PITCH*6 + 64)   // Qhi,Qlo,Khi,Klo,Vs,Ps + mask
#define FA_SMEM_BYTES (FA_SMEM_FLOATS * 4)

__global__ void __launch_bounds__(128, 2)
attn_tc_kernel(const int* __restrict__ mask, float* __restrict__ attn_out) {
    extern __shared__ float sm[];
    uint32_t* Qhi = (uint32_t*)sm;
    uint32_t* Qlo = Qhi + 64 * FA_PITCH;
    uint32_t* Khi = Qlo + 64 * FA_PITCH;
    uint32_t* Klo = Khi + 64 * FA_PITCH;
    uint32_t* Vs  = Klo + 64 * FA_PITCH;
    uint32_t* Ps  = Vs  + 64 * FA_PITCH;
    float*    Msk = (float*)(Ps + 64 * FA_PITCH);

    const int tid = threadIdx.x;
    const int lane = tid & 31;
    const int w = tid >> 5;                 // 0..3
    const int grp = lane >> 2;              // 0..7
    const int thr = lane & 3;               // 0..3
    const int b = blockIdx.y / H_DIM;
    const int h = blockIdx.y % H_DIM;
    const int qt0 = blockIdx.x * 64;
    const size_t qkv_base = (size_t)(b * T_DIM) * QKV_N + h * D_DIM;

    // Load Q tile 64x64, split into tf32 hi/lo
    #pragma unroll
    for (int i = 0; i < 8; i++) {
        int idx = tid + i * 128;            // 0..1023 float4s
        int r = idx >> 4, c4 = (idx & 15) * 4;
        float4 v = *(const float4*)&g_qkv[qkv_base + (size_t)(qt0 + r) * QKV_N + c4];
        int off = r * FA_PITCH + c4;
        float fx[4] = {v.x, v.y, v.z, v.w};
        #pragma unroll
        for (int j = 0; j < 4; j++) {
            uint32_t hb = f2tf32(fx[j]);
            Qhi[off + j] = hb;
            Qlo[off + j] = f2tf32(fx[j] - __uint_as_float(hb));
        }
    }

    float m0 = -1e30f, m1 = -1e30f, l0 = 0.0f, l1 = 0.0f;
    float o[8][4];
    #pragma unroll
    for (int nt = 0; nt < 8; nt++)
        #pragma unroll
        for (int r = 0; r < 4; r++) o[nt][r] = 0.0f;

    const int ra = w * 16 + grp;            // this thread's P/Q row (and +8)
    const float scale = 0.125f;

    for (int kt0 = 0; kt0 < T_DIM; kt0 += 64) {
        __syncthreads();                    // prior-iter K/V/Msk reads done
        // Load K (split) and V (single tf32): 64 rows x 16 float4 each
        #pragma unroll
        for (int i = 0; i < 8; i++) {
            int idx = tid + i * 128;
            int r = idx >> 4, c4 = (idx & 15) * 4;
            size_t base = qkv_base + (size_t)(kt0 + r) * QKV_N + c4;
            float4 kv = *(const float4*)&g_qkv[base + C_DIM];
            float4 vv = *(const float4*)&g_qkv[base + 2 * C_DIM];
            int off = r * FA_PITCH + c4;
            float kf[4] = {kv.x, kv.y, kv.z, kv.w};
            float vf[4] = {vv.x, vv.y, vv.z, vv.w};
            #pragma unroll
            for (int j = 0; j < 4; j++) {
                uint32_t hb = f2tf32(kf[j]);
                Khi[off + j] = hb;
                Klo[off + j] = f2tf32(kf[j] - __uint_as_float(hb));
                Vs [off + j] = f2tf32(vf[j]);
            }
        }
        if (tid < 64)
            Msk[tid] = (mask[b * T_DIM + kt0 + tid] == 0) ? -1e30f : 0.0f;
        __syncthreads();

        // --- S = Q @ K^T (split tf32: hi*hi + hi*lo + lo*hi) ---
        float s[8][4];
        #pragma unroll
        for (int nt = 0; nt < 8; nt++)
            #pragma unroll
            for (int r = 0; r < 4; r++) s[nt][r] = 0.0f;

        #pragma unroll
        for (int kt = 0; kt < 8; kt++) {
            int kk = kt * 8;
            uint32_t ah0 = Qhi[ra * FA_PITCH + kk + thr];
            uint32_t ah1 = Qhi[(ra + 8) * FA_PITCH + kk + thr];
            uint32_t ah2 = Qhi[ra * FA_PITCH + kk + thr + 4];
            uint32_t ah3 = Qhi[(ra + 8) * FA_PITCH + kk + thr + 4];
            uint32_t al0 = Qlo[ra * FA_PITCH + kk + thr];
            uint32_t al1 = Qlo[(ra + 8) * FA_PITCH + kk + thr];
            uint32_t al2 = Qlo[ra * FA_PITCH + kk + thr + 4];
            uint32_t al3 = Qlo[(ra + 8) * FA_PITCH + kk + thr + 4];
            #pragma unroll
            for (int nt = 0; nt < 8; nt++) {
                int c = nt * 8 + grp;
                uint32_t bh0 = Khi[c * FA_PITCH + kk + thr];
                uint32_t bh1 = Khi[c * FA_PITCH + kk + thr + 4];
                uint32_t bl0 = Klo[c * FA_PITCH + kk + thr];
                uint32_t bl1 = Klo[c * FA_PITCH + kk + thr + 4];
                mma_tf32(s[nt][0], s[nt][1], s[nt][2], s[nt][3],
                         ah0, ah1, ah2, ah3, bh0, bh1);
                mma_tf32(s[nt][0], s[nt][1], s[nt][2], s[nt][3],
                         ah0, ah1, ah2, ah3, bl0, bl1);
                mma_tf32(s[nt][0], s[nt][1], s[nt][2], s[nt][3],
                         al0, al1, al2, al3, bh0, bh1);
            }
        }

        // --- online softmax ---
        float mx0 = -1e30f, mx1 = -1e30f;
        #pragma unroll
        for (int nt = 0; nt < 8; nt++) {
            float bc0 = Msk[nt * 8 + 2 * thr];
            float bc1 = Msk[nt * 8 + 2 * thr + 1];
            s[nt][0] = fmaf(s[nt][0], scale, bc0);
            s[nt][1] = fmaf(s[nt][1], scale, bc1);
            s[nt][2] = fmaf(s[nt][2], scale, bc0);
            s[nt][3] = fmaf(s[nt][3], scale, bc1);
            mx0 = fmaxf(mx0, fmaxf(s[nt][0], s[nt][1]));
            mx1 = fmaxf(mx1, fmaxf(s[nt][2], s[nt][3]));
        }
        mx0 = fmaxf(mx0, __shfl_xor_sync(0xffffffffu, mx0, 1));
        mx0 = fmaxf(mx0, __shfl_xor_sync(0xffffffffu, mx0, 2));
        mx1 = fmaxf(mx1, __shfl_xor_sync(0xffffffffu, mx1, 1));
        mx1 = fmaxf(mx1, __shfl_xor_sync(0xffffffffu, mx1, 2));
        float mn0 = fmaxf(m0, mx0), mn1 = fmaxf(m1, mx1);
        float a0 = fast_exp(m0 - mn0), a1 = fast_exp(m1 - mn1);

        float rs0 = 0.0f, rs1 = 0.0f;
        #pragma unroll
        for (int nt = 0; nt < 8; nt++) {
            float p0 = fast_exp(s[nt][0] - mn0);
            float p1 = fast_exp(s[nt][1] - mn0);
            float p2 = fast_exp(s[nt][2] - mn1);
            float p3 = fast_exp(s[nt][3] - mn1);
            uint32_t t0 = f2tf32(p0), t1 = f2tf32(p1);
            uint32_t t2 = f2tf32(p2), t3 = f2tf32(p3);
            rs0 += __uint_as_float(t0) + __uint_as_float(t1);
            rs1 += __uint_as_float(t2) + __uint_as_float(t3);
            int cc = nt * 8 + 2 * thr;
            Ps[ra * FA_PITCH + cc]           = t0;
            Ps[ra * FA_PITCH + cc + 1]       = t1;
            Ps[(ra + 8) * FA_PITCH + cc]     = t2;
            Ps[(ra + 8) * FA_PITCH + cc + 1] = t3;
        }
        rs0 += __shfl_xor_sync(0xffffffffu, rs0, 1);
        rs0 += __shfl_xor_sync(0xffffffffu, rs0, 2);
        rs1 += __shfl_xor_sync(0xffffffffu, rs1, 1);
        rs1 += __shfl_xor_sync(0xffffffffu, rs1, 2);
        l0 = l0 * a0 + rs0;
        l1 = l1 * a1 + rs1;
        m0 = mn0; m1 = mn1;
        #pragma unroll
        for (int nt = 0; nt < 8; nt++) {
            o[nt][0] *= a0; o[nt][1] *= a0;
            o[nt][2] *= a1; o[nt][3] *= a1;
        }
        __syncwarp();   // P visible within warp (only this warp reads its rows)

        // --- O += P @ V ---
        #pragma unroll
        for (int kt = 0; kt < 8; kt++) {
            int kk = kt * 8;
            uint32_t pa0 = Ps[ra * FA_PITCH + kk + thr];
            uint32_t pa1 = Ps[(ra + 8) * FA_PITCH + kk + thr];
            uint32_t pa2 = Ps[ra * FA_PITCH + kk + thr + 4];
            uint32_t pa3 = Ps[(ra + 8) * FA_PITCH + kk + thr + 4];
            #pragma unroll
            for (int nt = 0; nt < 8; nt++) {
                int c = nt * 8 + grp;
                uint32_t vb0 = Vs[(kk + thr) * FA_PITCH + c];
                uint32_t vb1 = Vs[(kk + thr + 4) * FA_PITCH + c];
                mma_tf32(o[nt][0], o[nt][1], o[nt][2], o[nt][3],
                         pa0, pa1, pa2, pa3, vb0, vb1);
            }
        }
    }

    // Write output
    float il0 = 1.0f / l0, il1 = 1.0f / l1;
    int t0r = qt0 + ra, t1r = qt0 + ra + 8;
    #pragma unroll
    for (int nt = 0; nt < 8; nt++) {
        int col = h * D_DIM + nt * 8 + 2 * thr;
        *(float2*)&attn_out[(size_t)(b * T_DIM + t0r) * C_DIM + col] =
            make_float2(o[nt][0] * il0, o[nt][1] * il0);
        *(float2*)&attn_out[(size_t)(b * T_DIM + t1r) * C_DIM + col] =
            make_float2(o[nt][2] * il1, o[nt][3] * il1);
    }
}

// ---------------------------------------------------------------------------
// Fused LayerNorm + residual: out = res + LN(a) * gamma + beta
// ---------------------------------------------------------------------------
__global__ void ln_residual_kernel(const float* __restrict__ res,
                                   const float* __restrict__ a,
                                   const float* __restrict__ gamma,
                                   const float* __restrict__ beta,
                                   float* __restrict__ out) {
    const int row = blockIdx.x;
    const float* ar = a + (size_t)row * C_DIM;
    const float* rr = res + (size_t)row * C_DIM;
    float* outr = out + (size_t)row * C_DIM;

    float s = 0.0f, s2 = 0.0f;
    float v[3];
    #pragma unroll
    for (int k = 0; k < 3; k++) {
        v[k] = ar[threadIdx.x + k * 256];
        s += v[k];
        s2 += v[k] * v[k];
    }
    #pragma unroll
    for (int off = 16; off >= 1; off >>= 1) {
        s  += __shfl_xor_sync(0xffffffffu, s, off);
        s2 += __shfl_xor_sync(0xffffffffu, s2, off);
    }
    __shared__ float red_s[8], red_s2[8];
    int warp = threadIdx.x >> 5, lane = threadIdx.x & 31;
    if (lane == 0) { red_s[warp] = s; red_s2[warp] = s2; }
    __syncthreads();
    if (warp == 0) {
        s  = (lane < 8) ? red_s[lane]  : 0.0f;
        s2 = (lane < 8) ? red_s2[lane] : 0.0f;
        #pragma unroll
        for (int off = 4; off >= 1; off >>= 1) {
            s  += __shfl_xor_sync(0xffffffffu, s, off);
            s2 += __shfl_xor_sync(0xffffffffu, s2, off);
        }
        if (lane == 0) { red_s[0] = s; red_s2[0] = s2; }
    }
    __syncthreads();
    const float mean = red_s[0] * (1.0f / C_DIM);
    const float var  = red_s2[0] * (1.0f / C_DIM) - mean * mean;
    const float rstd = rsqrtf(var + 1e-5f);

    #pragma unroll
    for (int k = 0; k < 3; k++) {
        int i = threadIdx.x + k * 256;
        outr[i] = rr[i] + (v[k] - mean) * rstd * gamma[i] + beta[i];
    }
}

// ---------------------------------------------------------------------------
// Launch
// ---------------------------------------------------------------------------
extern "C" void kernel_launch(void* const* d_in, const int* in_sizes, int n_in,
                              void* d_out, int out_size) {
    const float* x    = (const float*)d_in[0];
    const int*   mask = (const int*)  d_in[1];
    const float* Wqkv = (const float*)d_in[2];
    const float* bqkv = (const float*)d_in[3];
    const float* Wp   = (const float*)d_in[4];
    const float* bp   = (const float*)d_in[5];
    const float* g1   = (const float*)d_in[6];
    const float* be1  = (const float*)d_in[7];
    const float* W1   = (const float*)d_in[8];
    const float* b1   = (const float*)d_in[9];
    const float* W2   = (const float*)d_in[10];
    const float* b2   = (const float*)d_in[11];
    const float* g2   = (const float*)d_in[12];
    const float* be2  = (const float*)d_in[13];
    float* out = (float*)d_out;

    float *qkv, *attn, *proj, *out1, *hid, *mlp;
    cudaGetSymbolAddress((void**)&qkv,  g_qkv);
    cudaGetSymbolAddress((void**)&attn, g_attn);
    cudaGetSymbolAddress((void**)&proj, g_proj);
    cudaGetSymbolAddress((void**)&out1, g_out1);
    cudaGetSymbolAddress((void**)&hid,  g_hid);
    cudaGetSymbolAddress((void**)&mlp,  g_mlp);

    cudaFuncSetAttribute(attn_tc_kernel,
                         cudaFuncAttributeMaxDynamicSharedMemorySize,
                         FA_SMEM_BYTES);

    dim3 blk(256);

    // 1) QKV projection
    gemm_tf32_kernel<false><<<dim3(QKV_N / GBN, M_ROWS / GBM), blk>>>(
        x, Wqkv, bqkv, qkv, M_ROWS, QKV_N, C_DIM);

    // 2) Flash attention (tensor cores)
    attn_tc_kernel<<<dim3(T_DIM / 64, B_DIM * H_DIM), 128, FA_SMEM_BYTES>>>(
        mask, attn);

    // 3) Output projection
    gemm_tf32_kernel<false><<<dim3(C_DIM / GBN, M_ROWS / GBM), blk>>>(
        attn, Wp, bp, proj, M_ROWS, C_DIM, C_DIM);

    // 4) out1 = x + LN(proj)
    ln_residual_kernel<<<M_ROWS, blk>>>(x, proj, g1, be1, out1);

    // 5) hid = gelu(out1 @ W1 + b1)
    gemm_tf32_kernel<true><<<dim3(DFF / GBN, M_ROWS / GBM), blk>>>(
        out1, W1, b1, hid, M_ROWS, DFF, C_DIM);

    // 6) mlp = hid @ W2 + b2
    gemm_tf32_kernel<false><<<dim3(C_DIM / GBN, M_ROWS / GBM), blk>>>(
        hid, W2, b2, mlp, M_ROWS, C_DIM, DFF);

    // 7) out = out1 + LN(mlp)
    ln_residual_kernel<<<M_ROWS, blk>>>(out1, mlp, g2, be2, out);
}

// round 5
// speedup vs baseline: 5.4729x; 1.6117x over previous
#include <cuda_runtime.h>
#include <cuda_fp16.h>
#include <math.h>
#include <stdint.h>

// Problem constants
#define B_DIM 2
#define T_DIM 2048
#define C_DIM 768
#define H_DIM 12
#define D_DIM 64
#define M_ROWS (B_DIM * T_DIM)      // 4096
#define DFF (4 * C_DIM)             // 3072
#define QKV_N (3 * C_DIM)           // 2304

// ---------------------------------------------------------------------------
// Scratch (device globals)
// ---------------------------------------------------------------------------
__device__ float g_qkv [M_ROWS * QKV_N];
__device__ float g_attn[M_ROWS * C_DIM];
__device__ float g_proj[M_ROWS * C_DIM];
__device__ float g_out1[M_ROWS * C_DIM];
__device__ float g_hid [M_ROWS * DFF];
__device__ float g_mlp [M_ROWS * C_DIM];

// Pack two floats into half2 (a -> low 16 bits / even k, b -> high / odd k)
__device__ __forceinline__ uint32_t pack2(float a, float b) {
    __half2 h = __floats2half2_rn(a, b);
    return *(uint32_t*)&h;
}

__device__ __forceinline__ void mma_f16(float& d0, float& d1, float& d2, float& d3,
                                        uint32_t a0, uint32_t a1, uint32_t a2, uint32_t a3,
                                        uint32_t b0, uint32_t b1) {
    asm volatile(
        "mma.sync.aligned.m16n8k16.row.col.f32.f16.f16.f32 "
        "{%0,%1,%2,%3}, {%4,%5,%6,%7}, {%8,%9}, {%0,%1,%2,%3};\n"
        : "+f"(d0), "+f"(d1), "+f"(d2), "+f"(d3)
        : "r"(a0), "r"(a1), "r"(a2), "r"(a3), "r"(b0), "r"(b1));
}

// FMA-only exp (avoids the slow MUFU pipe). |rel err| ~2.4e-6 for x <= 0.
__device__ __forceinline__ float fast_exp(float x) {
    const float LOG2E = 1.4426950408889634f;
    float y = x * LOG2E;
    y = fmaxf(y, -125.0f);
    float t = y + 12582912.0f;
    int j = __float_as_int(t);
    float r = t - 12582912.0f;
    float f = y - r;
    float p = 1.333356e-3f;
    p = fmaf(p, f, 9.618129e-3f);
    p = fmaf(p, f, 5.550411e-2f);
    p = fmaf(p, f, 2.402265e-1f);
    p = fmaf(p, f, 6.931472e-1f);
    p = fmaf(p, f, 1.0f);
    return p * __int_as_float((j + 127) << 23);
}

// ---------------------------------------------------------------------------
// fp16 tensor-core GEMM: C = A(MxK) @ W(KxN) + bias, opt. exact GELU.
// CTA tile 128x128, BK=32, 256 threads, warp tile 64x32. fp16 in, fp32 acc.
// ---------------------------------------------------------------------------
#define GBM 128
#define GBN 128
#define GBK 32
#define A2P 20
#define B2P 136

template <bool GELU>
__global__ void __launch_bounds__(256, 2)
gemm_f16_kernel(const float* __restrict__ A,
                const float* __restrict__ W,
                const float* __restrict__ bias,
                float* __restrict__ Cout,
                int M, int N, int K) {
    __shared__ uint32_t As2[GBM][A2P];
    __shared__ uint32_t Bs2[GBK / 2][B2P];

    const int tid = threadIdx.x;
    const int lane = tid & 31;
    const int w = tid >> 5;
    const int warp_m = (w & 1) * 64;
    const int warp_n = (w >> 1) * 32;
    const int bm = blockIdx.y * GBM;
    const int bn = blockIdx.x * GBN;
    const int grp = lane >> 2;
    const int thr = lane & 3;

    float acc[4][4][4];
    #pragma unroll
    for (int mt = 0; mt < 4; mt++)
        #pragma unroll
        for (int nt = 0; nt < 4; nt++)
            #pragma unroll
            for (int r = 0; r < 4; r++) acc[mt][nt][r] = 0.0f;

    for (int k0 = 0; k0 < K; k0 += GBK) {
        #pragma unroll
        for (int i = 0; i < 4; i++) {
            int idx = tid + i * 256;
            int r = idx >> 3, c4 = idx & 7;
            float4 v = *(const float4*)&A[(size_t)(bm + r) * K + k0 + c4 * 4];
            As2[r][c4 * 2 + 0] = pack2(v.x, v.y);
            As2[r][c4 * 2 + 1] = pack2(v.z, v.w);
        }
        #pragma unroll
        for (int i = 0; i < 2; i++) {
            int idx = tid + i * 256;
            int kp = idx >> 5, c4 = (idx & 31) * 4;
            const float* w0 = &W[(size_t)(k0 + 2 * kp) * N + bn + c4];
            float4 v0 = *(const float4*)w0;
            float4 v1 = *(const float4*)(w0 + N);
            Bs2[kp][c4 + 0] = pack2(v0.x, v1.x);
            Bs2[kp][c4 + 1] = pack2(v0.y, v1.y);
            Bs2[kp][c4 + 2] = pack2(v0.z, v1.z);
            Bs2[kp][c4 + 3] = pack2(v0.w, v1.w);
        }
        __syncthreads();

        #pragma unroll
        for (int kb = 0; kb < GBK / 2; kb += 8) {
            uint32_t af[4][4], bf[4][2];
            #pragma unroll
            for (int mt = 0; mt < 4; mt++) {
                int r = warp_m + mt * 16 + grp;
                af[mt][0] = As2[r][kb + thr];
                af[mt][1] = As2[r + 8][kb + thr];
                af[mt][2] = As2[r][kb + thr + 4];
                af[mt][3] = As2[r + 8][kb + thr + 4];
            }
            #pragma unroll
            for (int nt = 0; nt < 4; nt++) {
                int c = warp_n + nt * 8 + grp;
                bf[nt][0] = Bs2[kb + thr][c];
                bf[nt][1] = Bs2[kb + thr + 4][c];
            }
            #pragma unroll
            for (int mt = 0; mt < 4; mt++)
                #pragma unroll
                for (int nt = 0; nt < 4; nt++)
                    mma_f16(acc[mt][nt][0], acc[mt][nt][1],
                            acc[mt][nt][2], acc[mt][nt][3],
                            af[mt][0], af[mt][1], af[mt][2], af[mt][3],
                            bf[nt][0], bf[nt][1]);
        }
        __syncthreads();
    }

    #pragma unroll
    for (int mt = 0; mt < 4; mt++) {
        #pragma unroll
        for (int nt = 0; nt < 4; nt++) {
            int m0 = bm + warp_m + mt * 16 + grp;
            int n0 = bn + warp_n + nt * 8 + thr * 2;
            float bx = bias[n0], by = bias[n0 + 1];
            float v0 = acc[mt][nt][0] + bx;
            float v1 = acc[mt][nt][1] + by;
            float v2 = acc[mt][nt][2] + bx;
            float v3 = acc[mt][nt][3] + by;
            if (GELU) {
                v0 = 0.5f * v0 * (1.0f + erff(v0 * 0.70710678118654752f));
                v1 = 0.5f * v1 * (1.0f + erff(v1 * 0.70710678118654752f));
                v2 = 0.5f * v2 * (1.0f + erff(v2 * 0.70710678118654752f));
                v3 = 0.5f * v3 * (1.0f + erff(v3 * 0.70710678118654752f));
            }
            *(float2*)&Cout[(size_t)m0 * N + n0] = make_float2(v0, v1);
            *(float2*)&Cout[(size_t)(m0 + 8) * N + n0] = make_float2(v2, v3);
        }
    }
}

// ---------------------------------------------------------------------------
// fp16 tensor-core flash attention.
// Br=64 (4 warps x 16 rows), Bc=64. QK^T split fp16 (3 mma k16 ~17-bit),
// P@V single fp16. 55.5KB smem -> 4 CTAs/SM.
// ---------------------------------------------------------------------------
#define QP 36       // [row][kp] pitch
#define VP 72       // [kp][n]  pitch
#define FA_U32S (5 * 64 * QP + 32 * VP + 64)
#define FA_SMEM_BYTES (FA_U32S * 4)

__global__ void __launch_bounds__(128, 4)
attn_tc_kernel(const int* __restrict__ mask, float* __restrict__ attn_out) {
    extern __shared__ uint32_t sm[];
    uint32_t* Qhi = sm;                  // [64][QP]
    uint32_t* Qlo = Qhi + 64 * QP;
    uint32_t* Khi = Qlo + 64 * QP;       // [n][kp]
    uint32_t* Klo = Khi + 64 * QP;
    uint32_t* Ps  = Klo + 64 * QP;       // [row][kp]
    uint32_t* Vs  = Ps  + 64 * QP;       // [kp][n]
    float*    Msk = (float*)(Vs + 32 * VP);

    const int tid = threadIdx.x;
    const int lane = tid & 31;
    const int w = tid >> 5;
    const int grp = lane >> 2;
    const int thr = lane & 3;
    const int b = blockIdx.y / H_DIM;
    const int h = blockIdx.y % H_DIM;
    const int qt0 = blockIdx.x * 64;
    const size_t qkv_base = (size_t)(b * T_DIM) * QKV_N + h * D_DIM;

    // Load Q tile 64x64, split into fp16 hi/lo pairs (1024 float4 tasks)
    #pragma unroll
    for (int i = 0; i < 8; i++) {
        int idx = tid + i * 128;
        int r = idx >> 4, c4 = (idx & 15) * 4;
        float4 v = *(const float4*)&g_qkv[qkv_base + (size_t)(qt0 + r) * QKV_N + c4];
        float fx[4] = {v.x, v.y, v.z, v.w};
        float hi[4], lo[4];
        #pragma unroll
        for (int j = 0; j < 4; j++) {
            hi[j] = __half2float(__float2half_rn(fx[j]));
            lo[j] = fx[j] - hi[j];
        }
        int off = r * QP + c4 / 2;
        Qhi[off]     = pack2(hi[0], hi[1]);
        Qhi[off + 1] = pack2(hi[2], hi[3]);
        Qlo[off]     = pack2(lo[0], lo[1]);
        Qlo[off + 1] = pack2(lo[2], lo[3]);
    }

    float m0 = -1e30f, m1 = -1e30f, l0 = 0.0f, l1 = 0.0f;
    float o[8][4];
    #pragma unroll
    for (int nt = 0; nt < 8; nt++)
        #pragma unroll
        for (int r = 0; r < 4; r++) o[nt][r] = 0.0f;

    const int ra = w * 16 + grp;
    const float scale = 0.125f;

    for (int kt0 = 0; kt0 < T_DIM; kt0 += 64) {
        __syncthreads();
        // K: split fp16, [n][kp]. 64 rows x 16 float4 = 1024 tasks (i < 8!)
        #pragma unroll
        for (int i = 0; i < 8; i++) {
            int idx = tid + i * 128;
            int r = idx >> 4, c4 = (idx & 15) * 4;
            float4 kv = *(const float4*)&g_qkv[qkv_base + (size_t)(kt0 + r) * QKV_N + C_DIM + c4];
            float fx[4] = {kv.x, kv.y, kv.z, kv.w};
            float hi[4], lo[4];
            #pragma unroll
            for (int j = 0; j < 4; j++) {
                hi[j] = __half2float(__float2half_rn(fx[j]));
                lo[j] = fx[j] - hi[j];
            }
            int off = r * QP + c4 / 2;
            Khi[off]     = pack2(hi[0], hi[1]);
            Khi[off + 1] = pack2(hi[2], hi[3]);
            Klo[off]     = pack2(lo[0], lo[1]);
            Klo[off + 1] = pack2(lo[2], lo[3]);
        }
        // V: single fp16, [kp][n] (pairs across adjacent token rows).
        // 32 kp x 16 float4-pairs = 512 tasks, each covers two rows.
        #pragma unroll
        for (int i = 0; i < 4; i++) {
            int idx = tid + i * 128;
            int kp = idx >> 4, c4 = (idx & 15) * 4;
            const float* v0p = &g_qkv[qkv_base + (size_t)(kt0 + 2 * kp) * QKV_N + 2 * C_DIM + c4];
            float4 v0 = *(const float4*)v0p;
            float4 v1 = *(const float4*)(v0p + QKV_N);
            Vs[kp * VP + c4 + 0] = pack2(v0.x, v1.x);
            Vs[kp * VP + c4 + 1] = pack2(v0.y, v1.y);
            Vs[kp * VP + c4 + 2] = pack2(v0.z, v1.z);
            Vs[kp * VP + c4 + 3] = pack2(v0.w, v1.w);
        }
        if (tid < 64)
            Msk[tid] = (mask[b * T_DIM + kt0 + tid] == 0) ? -1e30f : 0.0f;
        __syncthreads();

        // --- S = Q @ K^T (split fp16: hi*hi + hi*lo + lo*hi), 4 k16 steps ---
        float s[8][4];
        #pragma unroll
        for (int nt = 0; nt < 8; nt++)
            #pragma unroll
            for (int r = 0; r < 4; r++) s[nt][r] = 0.0f;

        #pragma unroll
        for (int kt = 0; kt < 4; kt++) {
            int kb = kt * 8;
            int q0 = ra * QP + kb, q1 = (ra + 8) * QP + kb;
            uint32_t ah0 = Qhi[q0 + thr],     ah1 = Qhi[q1 + thr];
            uint32_t ah2 = Qhi[q0 + thr + 4], ah3 = Qhi[q1 + thr + 4];
            uint32_t al0 = Qlo[q0 + thr],     al1 = Qlo[q1 + thr];
            uint32_t al2 = Qlo[q0 + thr + 4], al3 = Qlo[q1 + thr + 4];
            #pragma unroll
            for (int nt = 0; nt < 8; nt++) {
                int c = (nt * 8 + grp) * QP + kb;
                uint32_t bh0 = Khi[c + thr], bh1 = Khi[c + thr + 4];
                uint32_t bl0 = Klo[c + thr], bl1 = Klo[c + thr + 4];
                mma_f16(s[nt][0], s[nt][1], s[nt][2], s[nt][3],
                        ah0, ah1, ah2, ah3, bh0, bh1);
                mma_f16(s[nt][0], s[nt][1], s[nt][2], s[nt][3],
                        ah0, ah1, ah2, ah3, bl0, bl1);
                mma_f16(s[nt][0], s[nt][1], s[nt][2], s[nt][3],
                        al0, al1, al2, al3, bh0, bh1);
            }
        }

        // --- online softmax ---
        float mx0 = -1e30f, mx1 = -1e30f;
        #pragma unroll
        for (int nt = 0; nt < 8; nt++) {
            float bc0 = Msk[nt * 8 + 2 * thr];
            float bc1 = Msk[nt * 8 + 2 * thr + 1];
            s[nt][0] = fmaf(s[nt][0], scale, bc0);
            s[nt][1] = fmaf(s[nt][1], scale, bc1);
            s[nt][2] = fmaf(s[nt][2], scale, bc0);
            s[nt][3] = fmaf(s[nt][3], scale, bc1);
            mx0 = fmaxf(mx0, fmaxf(s[nt][0], s[nt][1]));
            mx1 = fmaxf(mx1, fmaxf(s[nt][2], s[nt][3]));
        }
        mx0 = fmaxf(mx0, __shfl_xor_sync(0xffffffffu, mx0, 1));
        mx0 = fmaxf(mx0, __shfl_xor_sync(0xffffffffu, mx0, 2));
        mx1 = fmaxf(mx1, __shfl_xor_sync(0xffffffffu, mx1, 1));
        mx1 = fmaxf(mx1, __shfl_xor_sync(0xffffffffu, mx1, 2));
        float mn0 = fmaxf(m0, mx0), mn1 = fmaxf(m1, mx1);
        float a0 = fast_exp(m0 - mn0), a1 = fast_exp(m1 - mn1);

        float rs0 = 0.0f, rs1 = 0.0f;
        #pragma unroll
        for (int nt = 0; nt < 8; nt++) {
            float p0 = fast_exp(s[nt][0] - mn0);
            float p1 = fast_exp(s[nt][1] - mn0);
            float p2 = fast_exp(s[nt][2] - mn1);
            float p3 = fast_exp(s[nt][3] - mn1);
            rs0 += p0 + p1;
            rs1 += p2 + p3;
            int cp = nt * 4 + thr;
            Ps[ra * QP + cp]       = pack2(p0, p1);
            Ps[(ra + 8) * QP + cp] = pack2(p2, p3);
        }
        rs0 += __shfl_xor_sync(0xffffffffu, rs0, 1);
        rs0 += __shfl_xor_sync(0xffffffffu, rs0, 2);
        rs1 += __shfl_xor_sync(0xffffffffu, rs1, 1);
        rs1 += __shfl_xor_sync(0xffffffffu, rs1, 2);
        l0 = l0 * a0 + rs0;
        l1 = l1 * a1 + rs1;
        m0 = mn0; m1 = mn1;
        #pragma unroll
        for (int nt = 0; nt < 8; nt++) {
            o[nt][0] *= a0; o[nt][1] *= a0;
            o[nt][2] *= a1; o[nt][3] *= a1;
        }
        __syncwarp();   // P rows read only within the warp that wrote them

        // --- O += P @ V (single fp16), 4 k16 steps ---
        #pragma unroll
        for (int kt = 0; kt < 4; kt++) {
            int kb = kt * 8;
            int p0o = ra * QP + kb, p1o = (ra + 8) * QP + kb;
            uint32_t pa0 = Ps[p0o + thr],     pa1 = Ps[p1o + thr];
            uint32_t pa2 = Ps[p0o + thr + 4], pa3 = Ps[p1o + thr + 4];
            #pragma unroll
            for (int nt = 0; nt < 8; nt++) {
                int c = nt * 8 + grp;
                uint32_t vb0 = Vs[(kb + thr) * VP + c];
                uint32_t vb1 = Vs[(kb + thr + 4) * VP + c];
                mma_f16(o[nt][0], o[nt][1], o[nt][2], o[nt][3],
                        pa0, pa1, pa2, pa3, vb0, vb1);
            }
        }
    }

    // Write output
    float il0 = 1.0f / l0, il1 = 1.0f / l1;
    int t0r = qt0 + ra, t1r = qt0 + ra + 8;
    #pragma unroll
    for (int nt = 0; nt < 8; nt++) {
        int col = h * D_DIM + nt * 8 + 2 * thr;
        *(float2*)&attn_out[(size_t)(b * T_DIM + t0r) * C_DIM + col] =
            make_float2(o[nt][0] * il0, o[nt][1] * il0);
        *(float2*)&attn_out[(size_t)(b * T_DIM + t1r) * C_DIM + col] =
            make_float2(o[nt][2] * il1, o[nt][3] * il1);
    }
}

// ---------------------------------------------------------------------------
// Fused LayerNorm + residual: out = res + LN(a) * gamma + beta
// ---------------------------------------------------------------------------
__global__ void ln_residual_kernel(const float* __restrict__ res,
                                   const float* __restrict__ a,
                                   const float* __restrict__ gamma,
                                   const float* __restrict__ beta,
                                   float* __restrict__ out) {
    const int row = blockIdx.x;
    const float* ar = a + (size_t)row * C_DIM;
    const float* rr = res + (size_t)row * C_DIM;
    float* outr = out + (size_t)row * C_DIM;

    float s = 0.0f, s2 = 0.0f;
    float v[3];
    #pragma unroll
    for (int k = 0; k < 3; k++) {
        v[k] = ar[threadIdx.x + k * 256];
        s += v[k];
        s2 += v[k] * v[k];
    }
    #pragma unroll
    for (int off = 16; off >= 1; off >>= 1) {
        s  += __shfl_xor_sync(0xffffffffu, s, off);
        s2 += __shfl_xor_sync(0xffffffffu, s2, off);
    }
    __shared__ float red_s[8], red_s2[8];
    int warp = threadIdx.x >> 5, lane = threadIdx.x & 31;
    if (lane == 0) { red_s[warp] = s; red_s2[warp] = s2; }
    __syncthreads();
    if (warp == 0) {
        s  = (lane < 8) ? red_s[lane]  : 0.0f;
        s2 = (lane < 8) ? red_s2[lane] : 0.0f;
        #pragma unroll
        for (int off = 4; off >= 1; off >>= 1) {
            s  += __shfl_xor_sync(0xffffffffu, s, off);
            s2 += __shfl_xor_sync(0xffffffffu, s2, off);
        }
        if (lane == 0) { red_s[0] = s; red_s2[0] = s2; }
    }
    __syncthreads();
    const float mean = red_s[0] * (1.0f / C_DIM);
    const float var  = red_s2[0] * (1.0f / C_DIM) - mean * mean;
    const float rstd = rsqrtf(var + 1e-5f);

    #pragma unroll
    for (int k = 0; k < 3; k++) {
        int i = threadIdx.x + k * 256;
        outr[i] = rr[i] + (v[k] - mean) * rstd * gamma[i] + beta[i];
    }
}

// ---------------------------------------------------------------------------
// Launch
// ---------------------------------------------------------------------------
extern "C" void kernel_launch(void* const* d_in, const int* in_sizes, int n_in,
                              void* d_out, int out_size) {
    const float* x    = (const float*)d_in[0];
    const int*   mask = (const int*)  d_in[1];
    const float* Wqkv = (const float*)d_in[2];
    const float* bqkv = (const float*)d_in[3];
    const float* Wp   = (const float*)d_in[4];
    const float* bp   = (const float*)d_in[5];
    const float* g1   = (const float*)d_in[6];
    const float* be1  = (const float*)d_in[7];
    const float* W1   = (const float*)d_in[8];
    const float* b1   = (const float*)d_in[9];
    const float* W2   = (const float*)d_in[10];
    const float* b2   = (const float*)d_in[11];
    const float* g2   = (const float*)d_in[12];
    const float* be2  = (const float*)d_in[13];
    float* out = (float*)d_out;

    float *qkv, *attn, *proj, *out1, *hid, *mlp;
    cudaGetSymbolAddress((void**)&qkv,  g_qkv);
    cudaGetSymbolAddress((void**)&attn, g_attn);
    cudaGetSymbolAddress((void**)&proj, g_proj);
    cudaGetSymbolAddress((void**)&out1, g_out1);
    cudaGetSymbolAddress((void**)&hid,  g_hid);
    cudaGetSymbolAddress((void**)&mlp,  g_mlp);

    cudaFuncSetAttribute(attn_tc_kernel,
                         cudaFuncAttributeMaxDynamicSharedMemorySize,
                         FA_SMEM_BYTES);

    dim3 blk(256);

    // 1) QKV projection
    gemm_f16_kernel<false><<<dim3(QKV_N / GBN, M_ROWS / GBM), blk>>>(
        x, Wqkv, bqkv, qkv, M_ROWS, QKV_N, C_DIM);

    // 2) Flash attention (fp16 tensor cores)
    attn_tc_kernel<<<dim3(T_DIM / 64, B_DIM * H_DIM), 128, FA_SMEM_BYTES>>>(
        mask, attn);

    // 3) Output projection
    gemm_f16_kernel<false><<<dim3(C_DIM / GBN, M_ROWS / GBM), blk>>>(
        attn, Wp, bp, proj, M_ROWS, C_DIM, C_DIM);

    // 4) out1 = x + LN(proj)
    ln_residual_kernel<<<M_ROWS, blk>>>(x, proj, g1, be1, out1);

    // 5) hid = gelu(out1 @ W1 + b1)
    gemm_f16_kernel<true><<<dim3(DFF / GBN, M_ROWS / GBM), blk>>>(
        out1, W1, b1, hid, M_ROWS, DFF, C_DIM);

    // 6) mlp = hid @ W2 + b2
    gemm_f16_kernel<false><<<dim3(C_DIM / GBN, M_ROWS / GBM), blk>>>(
        hid, W2, b2, mlp, M_ROWS, C_DIM, DFF);

    // 7) out = out1 + LN(mlp)
    ln_residual_kernel<<<M_ROWS, blk>>>(out1, mlp, g2, be2, out);
}

// round 7
// speedup vs baseline: 5.6440x; 1.0313x over previous
#include <cuda_runtime.h>
#include <cuda_fp16.h>
#include <math.h>
#include <stdint.h>

// Problem constants
#define B_DIM 2
#define T_DIM 2048
#define C_DIM 768
#define H_DIM 12
#define D_DIM 64
#define M_ROWS (B_DIM * T_DIM)      // 4096
#define DFF (4 * C_DIM)             // 3072
#define QKV_N (3 * C_DIM)           // 2304
#define BH (B_DIM * H_DIM)          // 24

// ---------------------------------------------------------------------------
// Scratch (device globals)
// ---------------------------------------------------------------------------
__device__ uint32_t g_qhi[BH * T_DIM * 32];   // Q split-fp16 hi, [bh][t][d/2]
__device__ uint32_t g_qlo[BH * T_DIM * 32];
__device__ uint32_t g_khi[BH * T_DIM * 32];
__device__ uint32_t g_klo[BH * T_DIM * 32];
__device__ float    g_v  [BH * T_DIM * D_DIM];      // V fp32 [bh][t][d]
__device__ uint32_t g_vp [BH * D_DIM * (T_DIM/2)];  // V fp16 pairs [bh][d][tp]
__device__ float g_attn[M_ROWS * C_DIM];
__device__ float g_proj[M_ROWS * C_DIM];
__device__ float g_out1[M_ROWS * C_DIM];
__device__ float g_hid [M_ROWS * DFF];
__device__ float g_mlp [M_ROWS * C_DIM];

__device__ __forceinline__ uint32_t pack2(float a, float b) {
    __half2 h = __floats2half2_rn(a, b);
    return *(uint32_t*)&h;
}

// Split (a,b) into fp16 hi pair (returned) and residual lo pair (out param).
__device__ __forceinline__ uint32_t split_pack(float a, float b, uint32_t& lo) {
    __half ha = __float2half_rn(a), hb = __float2half_rn(b);
    lo = pack2(a - __half2float(ha), b - __half2float(hb));
    __half2 h2 = __halves2half2(ha, hb);
    return *(uint32_t*)&h2;
}

__device__ __forceinline__ void mma_f16(float& d0, float& d1, float& d2, float& d3,
                                        uint32_t a0, uint32_t a1, uint32_t a2, uint32_t a3,
                                        uint32_t b0, uint32_t b1) {
    asm volatile(
        "mma.sync.aligned.m16n8k16.row.col.f32.f16.f16.f32 "
        "{%0,%1,%2,%3}, {%4,%5,%6,%7}, {%8,%9}, {%0,%1,%2,%3};\n"
        : "+f"(d0), "+f"(d1), "+f"(d2), "+f"(d3)
        : "r"(a0), "r"(a1), "r"(a2), "r"(a3), "r"(b0), "r"(b1));
}

// FMA-only exp (avoids the slow MUFU pipe). |rel err| ~2.4e-6 for x <= 0.
__device__ __forceinline__ float fast_exp(float x) {
    const float LOG2E = 1.4426950408889634f;
    float y = x * LOG2E;
    y = fmaxf(y, -125.0f);
    float t = y + 12582912.0f;
    int j = __float_as_int(t);
    float r = t - 12582912.0f;
    float f = y - r;
    float p = 1.333356e-3f;
    p = fmaf(p, f, 9.618129e-3f);
    p = fmaf(p, f, 5.550411e-2f);
    p = fmaf(p, f, 2.402265e-1f);
    p = fmaf(p, f, 6.931472e-1f);
    p = fmaf(p, f, 1.0f);
    return p * __int_as_float((j + 127) << 23);
}

// ---------------------------------------------------------------------------
// fp16 tensor-core GEMM. MODE: 0 = plain bias, 1 = bias + exact GELU,
// 2 = QKV epilogue (writes split-fp16 Q/K and fp32 V; Cout unused).
// CTA tile 128x128, BK=32, 256 threads, warp tile 64x32. fp16 in, fp32 acc.
// ---------------------------------------------------------------------------
#define GBM 128
#define GBN 128
#define GBK 32
#define A2P 20
#define B2P 136

template <int MODE>
__global__ void __launch_bounds__(256, 2)
gemm_f16_kernel(const float* __restrict__ A,
                const float* __restrict__ W,
                const float* __restrict__ bias,
                float* __restrict__ Cout,
                int M, int N, int K,
                uint32_t* __restrict__ qhi, uint32_t* __restrict__ qlo,
                uint32_t* __restrict__ khi, uint32_t* __restrict__ klo,
                float* __restrict__ vout) {
    __shared__ uint32_t As2[GBM][A2P];
    __shared__ uint32_t Bs2[GBK / 2][B2P];

    const int tid = threadIdx.x;
    const int lane = tid & 31;
    const int w = tid >> 5;
    const int warp_m = (w & 1) * 64;
    const int warp_n = (w >> 1) * 32;
    const int bm = blockIdx.y * GBM;
    const int bn = blockIdx.x * GBN;
    const int grp = lane >> 2;
    const int thr = lane & 3;

    float acc[4][4][4];
    #pragma unroll
    for (int mt = 0; mt < 4; mt++)
        #pragma unroll
        for (int nt = 0; nt < 4; nt++)
            #pragma unroll
            for (int r = 0; r < 4; r++) acc[mt][nt][r] = 0.0f;

    for (int k0 = 0; k0 < K; k0 += GBK) {
        #pragma unroll
        for (int i = 0; i < 4; i++) {
            int idx = tid + i * 256;
            int r = idx >> 3, c4 = idx & 7;
            float4 v = *(const float4*)&A[(size_t)(bm + r) * K + k0 + c4 * 4];
            As2[r][c4 * 2 + 0] = pack2(v.x, v.y);
            As2[r][c4 * 2 + 1] = pack2(v.z, v.w);
        }
        #pragma unroll
        for (int i = 0; i < 2; i++) {
            int idx = tid + i * 256;
            int kp = idx >> 5, c4 = (idx & 31) * 4;
            const float* w0 = &W[(size_t)(k0 + 2 * kp) * N + bn + c4];
            float4 v0 = *(const float4*)w0;
            float4 v1 = *(const float4*)(w0 + N);
            Bs2[kp][c4 + 0] = pack2(v0.x, v1.x);
            Bs2[kp][c4 + 1] = pack2(v0.y, v1.y);
            Bs2[kp][c4 + 2] = pack2(v0.z, v1.z);
            Bs2[kp][c4 + 3] = pack2(v0.w, v1.w);
        }
        __syncthreads();

        #pragma unroll
        for (int kb = 0; kb < GBK / 2; kb += 8) {
            uint32_t af[4][4], bf[4][2];
            #pragma unroll
            for (int mt = 0; mt < 4; mt++) {
                int r = warp_m + mt * 16 + grp;
                af[mt][0] = As2[r][kb + thr];
                af[mt][1] = As2[r + 8][kb + thr];
                af[mt][2] = As2[r][kb + thr + 4];
                af[mt][3] = As2[r + 8][kb + thr + 4];
            }
            #pragma unroll
            for (int nt = 0; nt < 4; nt++) {
                int c = warp_n + nt * 8 + grp;
                bf[nt][0] = Bs2[kb + thr][c];
                bf[nt][1] = Bs2[kb + thr + 4][c];
            }
            #pragma unroll
            for (int mt = 0; mt < 4; mt++)
                #pragma unroll
                for (int nt = 0; nt < 4; nt++)
                    mma_f16(acc[mt][nt][0], acc[mt][nt][1],
                            acc[mt][nt][2], acc[mt][nt][3],
                            af[mt][0], af[mt][1], af[mt][2], af[mt][3],
                            bf[nt][0], bf[nt][1]);
        }
        __syncthreads();
    }

    #pragma unroll
    for (int mt = 0; mt < 4; mt++) {
        #pragma unroll
        for (int nt = 0; nt < 4; nt++) {
            int m0 = bm + warp_m + mt * 16 + grp;
            int n0 = bn + warp_n + nt * 8 + thr * 2;
            float bx = bias[n0], by = bias[n0 + 1];
            float v0 = acc[mt][nt][0] + bx;
            float v1 = acc[mt][nt][1] + by;
            float v2 = acc[mt][nt][2] + bx;
            float v3 = acc[mt][nt][3] + by;
            if (MODE == 1) {
                v0 = 0.5f * v0 * (1.0f + erff(v0 * 0.70710678118654752f));
                v1 = 0.5f * v1 * (1.0f + erff(v1 * 0.70710678118654752f));
                v2 = 0.5f * v2 * (1.0f + erff(v2 * 0.70710678118654752f));
                v3 = 0.5f * v3 * (1.0f + erff(v3 * 0.70710678118654752f));
            }
            if (MODE == 2) {
                // QKV epilogue: split-fp16 Q/K, fp32 V in [bh][t][d]
                int bb = m0 >> 11, t = m0 & 2047;
                if (n0 < C_DIM) {
                    int h = n0 >> 6, d = n0 & 63;
                    size_t off = ((size_t)(bb * H_DIM + h) * T_DIM + t) * 32 + (d >> 1);
                    uint32_t lo, hi;
                    hi = split_pack(v0, v1, lo);
                    qhi[off] = hi; qlo[off] = lo;
                    hi = split_pack(v2, v3, lo);
                    qhi[off + 8 * 32] = hi; qlo[off + 8 * 32] = lo;
                } else if (n0 < 2 * C_DIM) {
                    int h = (n0 - C_DIM) >> 6, d = (n0 - C_DIM) & 63;
                    size_t off = ((size_t)(bb * H_DIM + h) * T_DIM + t) * 32 + (d >> 1);
                    uint32_t lo, hi;
                    hi = split_pack(v0, v1, lo);
                    khi[off] = hi; klo[off] = lo;
                    hi = split_pack(v2, v3, lo);
                    khi[off + 8 * 32] = hi; klo[off + 8 * 32] = lo;
                } else {
                    int h = (n0 - 2 * C_DIM) >> 6, d = (n0 - 2 * C_DIM) & 63;
                    size_t off = ((size_t)(bb * H_DIM + h) * T_DIM + t) * 64 + d;
                    *(float2*)&vout[off] = make_float2(v0, v1);
                    *(float2*)&vout[off + 8 * 64] = make_float2(v2, v3);
                }
            } else {
                *(float2*)&Cout[(size_t)m0 * N + n0] = make_float2(v0, v1);
                *(float2*)&Cout[(size_t)(m0 + 8) * N + n0] = make_float2(v2, v3);
            }
        }
    }
}

// ---------------------------------------------------------------------------
// V repack: g_v [bh][t][d] fp32 -> g_vp [bh][d][tp] u32 (fp16 token pairs).
// ---------------------------------------------------------------------------
__global__ void repack_v_kernel() {
    int o = blockIdx.x * 256 + threadIdx.x;        // 0 .. 393215
    int tp0 = (o & 255) * 4;                       // 0..1020
    int row = o >> 8;                              // bh*64 + d
    const float* src = g_v + (size_t)(row >> 6) * T_DIM * D_DIM + (row & 63);
    uint32_t out[4];
    #pragma unroll
    for (int j = 0; j < 4; j++) {
        int t0 = (tp0 + j) * 2;
        out[j] = pack2(src[(size_t)t0 * D_DIM], src[(size_t)(t0 + 1) * D_DIM]);
    }
    *(uint4*)&g_vp[(size_t)row * (T_DIM / 2) + tp0] = *(uint4*)out;
}

// ---------------------------------------------------------------------------
// fp16 tensor-core flash attention, pre-split operands (no cvt in loop).
// Br=64 (4 warps x 16 rows), Bc=64. QK^T split fp16 (3 mma k16),
// P@V single fp16. 55.5KB smem -> 4 CTAs/SM.
// ---------------------------------------------------------------------------
#define QP 36       // [row][kp] pitch
#define FA_U32S (6 * 64 * QP + 64)
#define FA_SMEM_BYTES (FA_U32S * 4)

__global__ void __launch_bounds__(128, 4)
attn_tc_kernel(const int* __restrict__ mask, float* __restrict__ attn_out) {
    extern __shared__ uint32_t sm[];
    uint32_t* Qhi = sm;                  // [64][QP]
    uint32_t* Qlo = Qhi + 64 * QP;
    uint32_t* Khi = Qlo + 64 * QP;       // [n][kp]
    uint32_t* Klo = Khi + 64 * QP;
    uint32_t* Ps  = Klo + 64 * QP;       // [row][kp]
    uint32_t* Vs  = Ps  + 64 * QP;       // [d][tp]
    float*    Msk = (float*)(Vs + 64 * QP);

    const int tid = threadIdx.x;
    const int lane = tid & 31;
    const int w = tid >> 5;
    const int grp = lane >> 2;
    const int thr = lane & 3;
    const int bh = blockIdx.y;
    const int b = bh / H_DIM;
    const int qt0 = blockIdx.x * 64;

    const uint32_t* qhiG = g_qhi + (size_t)bh * T_DIM * 32;
    const uint32_t* qloG = g_qlo + (size_t)bh * T_DIM * 32;
    const uint32_t* khiG = g_khi + (size_t)bh * T_DIM * 32;
    const uint32_t* kloG = g_klo + (size_t)bh * T_DIM * 32;
    const uint32_t* vpG  = g_vp  + (size_t)bh * D_DIM * (T_DIM / 2);

    // Load Q tile: 64 rows x 8 uint4 (hi + lo)
    #pragma unroll
    for (int i = 0; i < 4; i++) {
        int idx = tid + i * 128;
        int r = idx >> 3, c4 = (idx & 7) * 4;
        uint4 vh = *(const uint4*)&qhiG[(size_t)(qt0 + r) * 32 + c4];
        uint4 vl = *(const uint4*)&qloG[(size_t)(qt0 + r) * 32 + c4];
        *(uint4*)&Qhi[r * QP + c4] = vh;
        *(uint4*)&Qlo[r * QP + c4] = vl;
    }

    float m0 = -1e30f, m1 = -1e30f, l0 = 0.0f, l1 = 0.0f;
    float o[8][4];
    #pragma unroll
    for (int nt = 0; nt < 8; nt++)
        #pragma unroll
        for (int r = 0; r < 4; r++) o[nt][r] = 0.0f;

    const int ra = w * 16 + grp;
    const float scale = 0.125f;

    for (int kt0 = 0; kt0 < T_DIM; kt0 += 64) {
        __syncthreads();
        // K tiles (hi+lo): 64 rows x 8 uint4
        #pragma unroll
        for (int i = 0; i < 4; i++) {
            int idx = tid + i * 128;
            int r = idx >> 3, c4 = (idx & 7) * 4;
            uint4 vh = *(const uint4*)&khiG[(size_t)(kt0 + r) * 32 + c4];
            uint4 vl = *(const uint4*)&kloG[(size_t)(kt0 + r) * 32 + c4];
            *(uint4*)&Khi[r * QP + c4] = vh;
            *(uint4*)&Klo[r * QP + c4] = vl;
        }
        // V tile: [d][tp] 64 rows x 8 uint4 (32 token-pairs)
        #pragma unroll
        for (int i = 0; i < 4; i++) {
            int idx = tid + i * 128;
            int c = idx >> 3, j4 = (idx & 7) * 4;
            uint4 vv = *(const uint4*)&vpG[(size_t)c * (T_DIM / 2) + (kt0 >> 1) + j4];
            *(uint4*)&Vs[c * QP + j4] = vv;
        }
        if (tid < 64)
            Msk[tid] = (mask[b * T_DIM + kt0 + tid] == 0) ? -1e30f : 0.0f;
        __syncthreads();

        // --- S = Q @ K^T (split fp16: hi*hi + hi*lo + lo*hi), 4 k16 steps ---
        float s[8][4];
        #pragma unroll
        for (int nt = 0; nt < 8; nt++)
            #pragma unroll
            for (int r = 0; r < 4; r++) s[nt][r] = 0.0f;

        #pragma unroll
        for (int kt = 0; kt < 4; kt++) {
            int kb = kt * 8;
            int q0 = ra * QP + kb, q1 = (ra + 8) * QP + kb;
            uint32_t ah0 = Qhi[q0 + thr],     ah1 = Qhi[q1 + thr];
            uint32_t ah2 = Qhi[q0 + thr + 4], ah3 = Qhi[q1 + thr + 4];
            uint32_t al0 = Qlo[q0 + thr],     al1 = Qlo[q1 + thr];
            uint32_t al2 = Qlo[q0 + thr + 4], al3 = Qlo[q1 + thr + 4];
            #pragma unroll
            for (int nt = 0; nt < 8; nt++) {
                int c = (nt * 8 + grp) * QP + kb;
                uint32_t bh0 = Khi[c + thr], bh1 = Khi[c + thr + 4];
                uint32_t bl0 = Klo[c + thr], bl1 = Klo[c + thr + 4];
                mma_f16(s[nt][0], s[nt][1], s[nt][2], s[nt][3],
                        ah0, ah1, ah2, ah3, bh0, bh1);
                mma_f16(s[nt][0], s[nt][1], s[nt][2], s[nt][3],
                        ah0, ah1, ah2, ah3, bl0, bl1);
                mma_f16(s[nt][0], s[nt][1], s[nt][2], s[nt][3],
                        al0, al1, al2, al3, bh0, bh1);
            }
        }

        // --- online softmax ---
        float mx0 = -1e30f, mx1 = -1e30f;
        #pragma unroll
        for (int nt = 0; nt < 8; nt++) {
            float bc0 = Msk[nt * 8 + 2 * thr];
            float bc1 = Msk[nt * 8 + 2 * thr + 1];
            s[nt][0] = fmaf(s[nt][0], scale, bc0);
            s[nt][1] = fmaf(s[nt][1], scale, bc1);
            s[nt][2] = fmaf(s[nt][2], scale, bc0);
            s[nt][3] = fmaf(s[nt][3], scale, bc1);
            mx0 = fmaxf(mx0, fmaxf(s[nt][0], s[nt][1]));
            mx1 = fmaxf(mx1, fmaxf(s[nt][2], s[nt][3]));
        }
        mx0 = fmaxf(mx0, __shfl_xor_sync(0xffffffffu, mx0, 1));
        mx0 = fmaxf(mx0, __shfl_xor_sync(0xffffffffu, mx0, 2));
        mx1 = fmaxf(mx1, __shfl_xor_sync(0xffffffffu, mx1, 1));
        mx1 = fmaxf(mx1, __shfl_xor_sync(0xffffffffu, mx1, 2));
        float mn0 = fmaxf(m0, mx0), mn1 = fmaxf(m1, mx1);
        float a0 = fast_exp(m0 - mn0), a1 = fast_exp(m1 - mn1);

        float rs0 = 0.0f, rs1 = 0.0f;
        #pragma unroll
        for (int nt = 0; nt < 8; nt++) {
            float p0 = fast_exp(s[nt][0] - mn0);
            float p1 = fast_exp(s[nt][1] - mn0);
            float p2 = fast_exp(s[nt][2] - mn1);
            float p3 = fast_exp(s[nt][3] - mn1);
            rs0 += p0 + p1;
            rs1 += p2 + p3;
            int cp = nt * 4 + thr;
            Ps[ra * QP + cp]       = pack2(p0, p1);
            Ps[(ra + 8) * QP + cp] = pack2(p2, p3);
        }
        rs0 += __shfl_xor_sync(0xffffffffu, rs0, 1);
        rs0 += __shfl_xor_sync(0xffffffffu, rs0, 2);
        rs1 += __shfl_xor_sync(0xffffffffu, rs1, 1);
        rs1 += __shfl_xor_sync(0xffffffffu, rs1, 2);
        l0 = l0 * a0 + rs0;
        l1 = l1 * a1 + rs1;
        m0 = mn0; m1 = mn1;
        #pragma unroll
        for (int nt = 0; nt < 8; nt++) {
            o[nt][0] *= a0; o[nt][1] *= a0;
            o[nt][2] *= a1; o[nt][3] *= a1;
        }
        __syncwarp();   // P rows read only within the warp that wrote them

        // --- O += P @ V (single fp16), 4 k16 steps ---
        #pragma unroll
        for (int kt = 0; kt < 4; kt++) {
            int kb = kt * 8;
            int p0o = ra * QP + kb, p1o = (ra + 8) * QP + kb;
            uint32_t pa0 = Ps[p0o + thr],     pa1 = Ps[p1o + thr];
            uint32_t pa2 = Ps[p0o + thr + 4], pa3 = Ps[p1o + thr + 4];
            #pragma unroll
            for (int nt = 0; nt < 8; nt++) {
                int c = (nt * 8 + grp) * QP;
                uint32_t vb0 = Vs[c + kb + thr];
                uint32_t vb1 = Vs[c + kb + thr + 4];
                mma_f16(o[nt][0], o[nt][1], o[nt][2], o[nt][3],
                        pa0, pa1, pa2, pa3, vb0, vb1);
            }
        }
    }

    // Write output (B,T,C)
    const int h = bh % H_DIM;
    float il0 = 1.0f / l0, il1 = 1.0f / l1;
    int t0r = qt0 + ra, t1r = qt0 + ra + 8;
    #pragma unroll
    for (int nt = 0; nt < 8; nt++) {
        int col = h * D_DIM + nt * 8 + 2 * thr;
        *(float2*)&attn_out[(size_t)(b * T_DIM + t0r) * C_DIM + col] =
            make_float2(o[nt][0] * il0, o[nt][1] * il0);
        *(float2*)&attn_out[(size_t)(b * T_DIM + t1r) * C_DIM + col] =
            make_float2(o[nt][2] * il1, o[nt][3] * il1);
    }
}

// ---------------------------------------------------------------------------
// Fused LayerNorm + residual: out = res + LN(a) * gamma + beta
// ---------------------------------------------------------------------------
__global__ void ln_residual_kernel(const float* __restrict__ res,
                                   const float* __restrict__ a,
                                   const float* __restrict__ gamma,
                                   const float* __restrict__ beta,
                                   float* __restrict__ out) {
    const int row = blockIdx.x;
    const float* ar = a + (size_t)row * C_DIM;
    const float* rr = res + (size_t)row * C_DIM;
    float* outr = out + (size_t)row * C_DIM;

    float s = 0.0f, s2 = 0.0f;
    float v[3];
    #pragma unroll
    for (int k = 0; k < 3; k++) {
        v[k] = ar[threadIdx.x + k * 256];
        s += v[k];
        s2 += v[k] * v[k];
    }
    #pragma unroll
    for (int off = 16; off >= 1; off >>= 1) {
        s  += __shfl_xor_sync(0xffffffffu, s, off);
        s2 += __shfl_xor_sync(0xffffffffu, s2, off);
    }
    __shared__ float red_s[8], red_s2[8];
    int warp = threadIdx.x >> 5, lane = threadIdx.x & 31;
    if (lane == 0) { red_s[warp] = s; red_s2[warp] = s2; }
    __syncthreads();
    if (warp == 0) {
        s  = (lane < 8) ? red_s[lane]  : 0.0f;
        s2 = (lane < 8) ? red_s2[lane] : 0.0f;
        #pragma unroll
        for (int off = 4; off >= 1; off >>= 1) {
            s  += __shfl_xor_sync(0xffffffffu, s, off);
            s2 += __shfl_xor_sync(0xffffffffu, s2, off);
        }
        if (lane == 0) { red_s[0] = s; red_s2[0] = s2; }
    }
    __syncthreads();
    const float mean = red_s[0] * (1.0f / C_DIM);
    const float var  = red_s2[0] * (1.0f / C_DIM) - mean * mean;
    const float rstd = rsqrtf(var + 1e-5f);

    #pragma unroll
    for (int k = 0; k < 3; k++) {
        int i = threadIdx.x + k * 256;
        outr[i] = rr[i] + (v[k] - mean) * rstd * gamma[i] + beta[i];
    }
}

// ---------------------------------------------------------------------------
// Launch
// ---------------------------------------------------------------------------
extern "C" void kernel_launch(void* const* d_in, const int* in_sizes, int n_in,
                              void* d_out, int out_size) {
    const float* x    = (const float*)d_in[0];
    const int*   mask = (const int*)  d_in[1];
    const float* Wqkv = (const float*)d_in[2];
    const float* bqkv = (const float*)d_in[3];
    const float* Wp   = (const float*)d_in[4];
    const float* bp   = (const float*)d_in[5];
    const float* g1   = (const float*)d_in[6];
    const float* be1  = (const float*)d_in[7];
    const float* W1   = (const float*)d_in[8];
    const float* b1   = (const float*)d_in[9];
    const float* W2   = (const float*)d_in[10];
    const float* b2   = (const float*)d_in[11];
    const float* g2   = (const float*)d_in[12];
    const float* be2  = (const float*)d_in[13];
    float* out = (float*)d_out;

    uint32_t *qhi, *qlo, *khi, *klo;
    float *vraw, *attn, *proj, *out1, *hid, *mlp;
    cudaGetSymbolAddress((void**)&qhi,  g_qhi);
    cudaGetSymbolAddress((void**)&qlo,  g_qlo);
    cudaGetSymbolAddress((void**)&khi,  g_khi);
    cudaGetSymbolAddress((void**)&klo,  g_klo);
    cudaGetSymbolAddress((void**)&vraw, g_v);
    cudaGetSymbolAddress((void**)&attn, g_attn);
    cudaGetSymbolAddress((void**)&proj, g_proj);
    cudaGetSymbolAddress((void**)&out1, g_out1);
    cudaGetSymbolAddress((void**)&hid,  g_hid);
    cudaGetSymbolAddress((void**)&mlp,  g_mlp);

    cudaFuncSetAttribute(attn_tc_kernel,
                         cudaFuncAttributeMaxDynamicSharedMemorySize,
                         FA_SMEM_BYTES);

    dim3 blk(256);

    // 1) QKV projection, epilogue writes split-fp16 Q/K + fp32 V
    gemm_f16_kernel<2><<<dim3(QKV_N / GBN, M_ROWS / GBM), blk>>>(
        x, Wqkv, bqkv, nullptr, M_ROWS, QKV_N, C_DIM,
        qhi, qlo, khi, klo, vraw);

    // 1b) V repack into [bh][d][tp] fp16 token pairs
    repack_v_kernel<<<1536, 256>>>();

    // 2) Flash attention
    attn_tc_kernel<<<dim3(T_DIM / 64, BH), 128, FA_SMEM_BYTES>>>(mask, attn);

    // 3) Output projection
    gemm_f16_kernel<0><<<dim3(C_DIM / GBN, M_ROWS / GBM), blk>>>(
        attn, Wp, bp, proj, M_ROWS, C_DIM, C_DIM,
        nullptr, nullptr, nullptr, nullptr, nullptr);

    // 4) out1 = x + LN(proj)
    ln_residual_kernel<<<M_ROWS, blk>>>(x, proj, g1, be1, out1);

    // 5) hid = gelu(out1 @ W1 + b1)
    gemm_f16_kernel<1><<<dim3(DFF / GBN, M_ROWS / GBM), blk>>>(
        out1, W1, b1, hid, M_ROWS, DFF, C_DIM,
        nullptr, nullptr, nullptr, nullptr, nullptr);

    // 6) mlp = hid @ W2 + b2
    gemm_f16_kernel<0><<<dim3(C_DIM / GBN, M_ROWS / GBM), blk>>>(
        hid, W2, b2, mlp, M_ROWS, C_DIM, DFF,
        nullptr, nullptr, nullptr, nullptr, nullptr);

    // 7) out = out1 + LN(mlp)
    ln_residual_kernel<<<M_ROWS, blk>>>(out1, mlp, g2, be2, out);
}

// round 9
// speedup vs baseline: 6.0177x; 1.0662x over previous
#include <cuda_runtime.h>
#include <cuda_fp16.h>
#include <math.h>
#include <stdint.h>

// Problem constants
#define B_DIM 2
#define T_DIM 2048
#define C_DIM 768
#define H_DIM 12
#define D_DIM 64
#define M_ROWS (B_DIM * T_DIM)      // 4096
#define DFF (4 * C_DIM)             // 3072
#define QKV_N (3 * C_DIM)           // 2304
#define BH (B_DIM * H_DIM)          // 24

// ---------------------------------------------------------------------------
// Scratch (device globals)
// ---------------------------------------------------------------------------
__device__ uint32_t g_qhi[BH * T_DIM * 32];   // Q split-fp16 hi, [bh][t][d/2]
__device__ uint32_t g_qlo[BH * T_DIM * 32];
__device__ uint32_t g_khi[BH * T_DIM * 32];
__device__ uint32_t g_klo[BH * T_DIM * 32];
__device__ float    g_v  [BH * T_DIM * D_DIM];      // V fp32 [bh][t][d]
__device__ uint32_t g_vp [BH * D_DIM * (T_DIM/2)];  // V fp16 pairs [bh][d][tp]
__device__ float g_attn[M_ROWS * C_DIM];
__device__ float g_proj[M_ROWS * C_DIM];
__device__ float g_out1[M_ROWS * C_DIM];
__device__ float g_hid [M_ROWS * DFF];
__device__ float g_mlp [M_ROWS * C_DIM];

__device__ __forceinline__ uint32_t pack2(float a, float b) {
    __half2 h = __floats2half2_rn(a, b);
    return *(uint32_t*)&h;
}

__device__ __forceinline__ uint32_t split_pack(float a, float b, uint32_t& lo) {
    __half ha = __float2half_rn(a), hb = __float2half_rn(b);
    lo = pack2(a - __half2float(ha), b - __half2float(hb));
    __half2 h2 = __halves2half2(ha, hb);
    return *(uint32_t*)&h2;
}

__device__ __forceinline__ void mma_f16(float& d0, float& d1, float& d2, float& d3,
                                        uint32_t a0, uint32_t a1, uint32_t a2, uint32_t a3,
                                        uint32_t b0, uint32_t b1) {
    asm volatile(
        "mma.sync.aligned.m16n8k16.row.col.f32.f16.f16.f32 "
        "{%0,%1,%2,%3}, {%4,%5,%6,%7}, {%8,%9}, {%0,%1,%2,%3};\n"
        : "+f"(d0), "+f"(d1), "+f"(d2), "+f"(d3)
        : "r"(a0), "r"(a1), "r"(a2), "r"(a3), "r"(b0), "r"(b1));
}

// FMA-only exp (avoids the slow MUFU pipe). |rel err| ~2.4e-6 for x <= 0.
__device__ __forceinline__ float fast_exp(float x) {
    const float LOG2E = 1.4426950408889634f;
    float y = x * LOG2E;
    y = fmaxf(y, -125.0f);
    float t = y + 12582912.0f;
    int j = __float_as_int(t);
    float r = t - 12582912.0f;
    float f = y - r;
    float p = 1.333356e-3f;
    p = fmaf(p, f, 9.618129e-3f);
    p = fmaf(p, f, 5.550411e-2f);
    p = fmaf(p, f, 2.402265e-1f);
    p = fmaf(p, f, 6.931472e-1f);
    p = fmaf(p, f, 1.0f);
    return p * __int_as_float((j + 127) << 23);
}

// ---------------------------------------------------------------------------
// fp16 tensor-core GEMM, 2-stage software pipeline (register prefetch +
// double-buffered smem). MODE: 0 = bias, 1 = bias+GELU, 2 = QKV epilogue.
// CTA tile 128x128, BK=32, 256 threads, warp tile 64x32.
// ---------------------------------------------------------------------------
#define GBM 128
#define GBN 128
#define GBK 32
#define A2P 20
#define B2P 136

template <int MODE>
__global__ void __launch_bounds__(256, 2)
gemm_f16_kernel(const float* __restrict__ A,
                const float* __restrict__ W,
                const float* __restrict__ bias,
                float* __restrict__ Cout,
                int M, int N, int K,
                uint32_t* __restrict__ qhi, uint32_t* __restrict__ qlo,
                uint32_t* __restrict__ khi, uint32_t* __restrict__ klo,
                float* __restrict__ vout) {
    __shared__ uint32_t As2[2][GBM][A2P];
    __shared__ uint32_t Bs2[2][GBK / 2][B2P];

    const int tid = threadIdx.x;
    const int lane = tid & 31;
    const int w = tid >> 5;
    const int warp_m = (w & 1) * 64;
    const int warp_n = (w >> 1) * 32;
    const int bm = blockIdx.y * GBM;
    const int bn = blockIdx.x * GBN;
    const int grp = lane >> 2;
    const int thr = lane & 3;

    // Per-thread load task coordinates (fixed across iterations)
    const int a_r0 = tid >> 3;              // + i*32 rows
    const int a_c4 = (tid & 7) * 4;         // k offset within tile
    const int b_kp0 = tid >> 5;             // + i*8 k-pairs
    const int b_c4 = (tid & 31) * 4;        // n offset within tile

    uint32_t a_pre[4][2];
    uint32_t b_pre[2][4];

    float acc[4][4][4];
    #pragma unroll
    for (int mt = 0; mt < 4; mt++)
        #pragma unroll
        for (int nt = 0; nt < 4; nt++)
            #pragma unroll
            for (int r = 0; r < 4; r++) acc[mt][nt][r] = 0.0f;

    // ---- load tile k0 into registers (converted to packed fp16) ----
    auto load_tiles = [&](int k0) {
        #pragma unroll
        for (int i = 0; i < 4; i++) {
            float4 v = *(const float4*)&A[(size_t)(bm + a_r0 + i * 32) * K + k0 + a_c4];
            a_pre[i][0] = pack2(v.x, v.y);
            a_pre[i][1] = pack2(v.z, v.w);
        }
        #pragma unroll
        for (int i = 0; i < 2; i++) {
            const float* w0 = &W[(size_t)(k0 + 2 * (b_kp0 + i * 8)) * N + bn + b_c4];
            float4 v0 = *(const float4*)w0;
            float4 v1 = *(const float4*)(w0 + N);
            b_pre[i][0] = pack2(v0.x, v1.x);
            b_pre[i][1] = pack2(v0.y, v1.y);
            b_pre[i][2] = pack2(v0.z, v1.z);
            b_pre[i][3] = pack2(v0.w, v1.w);
        }
    };
    auto store_tiles = [&](int st) {
        #pragma unroll
        for (int i = 0; i < 4; i++) {
            As2[st][a_r0 + i * 32][a_c4 / 2 + 0] = a_pre[i][0];
            As2[st][a_r0 + i * 32][a_c4 / 2 + 1] = a_pre[i][1];
        }
        #pragma unroll
        for (int i = 0; i < 2; i++) {
            Bs2[st][b_kp0 + i * 8][b_c4 + 0] = b_pre[i][0];
            Bs2[st][b_kp0 + i * 8][b_c4 + 1] = b_pre[i][1];
            Bs2[st][b_kp0 + i * 8][b_c4 + 2] = b_pre[i][2];
            Bs2[st][b_kp0 + i * 8][b_c4 + 3] = b_pre[i][3];
        }
    };

    load_tiles(0);
    store_tiles(0);
    __syncthreads();

    const int nk = K / GBK;
    for (int ki = 0; ki < nk; ki++) {
        const int st = ki & 1;
        const bool has_next = (ki + 1 < nk);
        if (has_next) load_tiles((ki + 1) * GBK);   // gmem loads overlap mma

        #pragma unroll
        for (int kb = 0; kb < GBK / 2; kb += 8) {
            uint32_t af[4][4], bf[4][2];
            #pragma unroll
            for (int mt = 0; mt < 4; mt++) {
                int r = warp_m + mt * 16 + grp;
                af[mt][0] = As2[st][r][kb + thr];
                af[mt][1] = As2[st][r + 8][kb + thr];
                af[mt][2] = As2[st][r][kb + thr + 4];
                af[mt][3] = As2[st][r + 8][kb + thr + 4];
            }
            #pragma unroll
            for (int nt = 0; nt < 4; nt++) {
                int c = warp_n + nt * 8 + grp;
                bf[nt][0] = Bs2[st][kb + thr][c];
                bf[nt][1] = Bs2[st][kb + thr + 4][c];
            }
            #pragma unroll
            for (int mt = 0; mt < 4; mt++)
                #pragma unroll
                for (int nt = 0; nt < 4; nt++)
                    mma_f16(acc[mt][nt][0], acc[mt][nt][1],
                            acc[mt][nt][2], acc[mt][nt][3],
                            af[mt][0], af[mt][1], af[mt][2], af[mt][3],
                            bf[nt][0], bf[nt][1]);
        }

        if (has_next) store_tiles(st ^ 1);   // other stage: no reader conflict
        __syncthreads();
    }

    #pragma unroll
    for (int mt = 0; mt < 4; mt++) {
        #pragma unroll
        for (int nt = 0; nt < 4; nt++) {
            int m0 = bm + warp_m + mt * 16 + grp;
            int n0 = bn + warp_n + nt * 8 + thr * 2;
            float bx = bias[n0], by = bias[n0 + 1];
            float v0 = acc[mt][nt][0] + bx;
            float v1 = acc[mt][nt][1] + by;
            float v2 = acc[mt][nt][2] + bx;
            float v3 = acc[mt][nt][3] + by;
            if (MODE == 1) {
                v0 = 0.5f * v0 * (1.0f + erff(v0 * 0.70710678118654752f));
                v1 = 0.5f * v1 * (1.0f + erff(v1 * 0.70710678118654752f));
                v2 = 0.5f * v2 * (1.0f + erff(v2 * 0.70710678118654752f));
                v3 = 0.5f * v3 * (1.0f + erff(v3 * 0.70710678118654752f));
            }
            if (MODE == 2) {
                int bb = m0 >> 11, t = m0 & 2047;
                if (n0 < C_DIM) {
                    int h = n0 >> 6, d = n0 & 63;
                    size_t off = ((size_t)(bb * H_DIM + h) * T_DIM + t) * 32 + (d >> 1);
                    uint32_t lo, hi;
                    hi = split_pack(v0, v1, lo);
                    qhi[off] = hi; qlo[off] = lo;
                    hi = split_pack(v2, v3, lo);
                    qhi[off + 8 * 32] = hi; qlo[off + 8 * 32] = lo;
                } else if (n0 < 2 * C_DIM) {
                    int h = (n0 - C_DIM) >> 6, d = (n0 - C_DIM) & 63;
                    size_t off = ((size_t)(bb * H_DIM + h) * T_DIM + t) * 32 + (d >> 1);
                    uint32_t lo, hi;
                    hi = split_pack(v0, v1, lo);
                    khi[off] = hi; klo[off] = lo;
                    hi = split_pack(v2, v3, lo);
                    khi[off + 8 * 32] = hi; klo[off + 8 * 32] = lo;
                } else {
                    int h = (n0 - 2 * C_DIM) >> 6, d = (n0 - 2 * C_DIM) & 63;
                    size_t off = ((size_t)(bb * H_DIM + h) * T_DIM + t) * 64 + d;
                    *(float2*)&vout[off] = make_float2(v0, v1);
                    *(float2*)&vout[off + 8 * 64] = make_float2(v2, v3);
                }
            } else {
                *(float2*)&Cout[(size_t)m0 * N + n0] = make_float2(v0, v1);
                *(float2*)&Cout[(size_t)(m0 + 8) * N + n0] = make_float2(v2, v3);
            }
        }
    }
}

// ---------------------------------------------------------------------------
// V repack: g_v [bh][t][d] fp32 -> g_vp [bh][d][tp] u32 (fp16 token pairs).
// ---------------------------------------------------------------------------
__global__ void repack_v_kernel() {
    int o = blockIdx.x * 256 + threadIdx.x;
    int tp0 = (o & 255) * 4;
    int row = o >> 8;
    const float* src = g_v + (size_t)(row >> 6) * T_DIM * D_DIM + (row & 63);
    uint32_t out[4];
    #pragma unroll
    for (int j = 0; j < 4; j++) {
        int t0 = (tp0 + j) * 2;
        out[j] = pack2(src[(size_t)t0 * D_DIM], src[(size_t)(t0 + 1) * D_DIM]);
    }
    *(uint4*)&g_vp[(size_t)row * (T_DIM / 2) + tp0] = *(uint4*)out;
}

// ---------------------------------------------------------------------------
// fp16 tensor-core flash attention (unchanged from R7).
// ---------------------------------------------------------------------------
#define QP 36
#define FA_U32S (6 * 64 * QP + 64)
#define FA_SMEM_BYTES (FA_U32S * 4)

__global__ void __launch_bounds__(128, 4)
attn_tc_kernel(const int* __restrict__ mask, float* __restrict__ attn_out) {
    extern __shared__ uint32_t sm[];
    uint32_t* Qhi = sm;
    uint32_t* Qlo = Qhi + 64 * QP;
    uint32_t* Khi = Qlo + 64 * QP;
    uint32_t* Klo = Khi + 64 * QP;
    uint32_t* Ps  = Klo + 64 * QP;
    uint32_t* Vs  = Ps  + 64 * QP;
    float*    Msk = (float*)(Vs + 64 * QP);

    const int tid = threadIdx.x;
    const int lane = tid & 31;
    const int w = tid >> 5;
    const int grp = lane >> 2;
    const int thr = lane & 3;
    const int bh = blockIdx.y;
    const int b = bh / H_DIM;
    const int qt0 = blockIdx.x * 64;

    const uint32_t* qhiG = g_qhi + (size_t)bh * T_DIM * 32;
    const uint32_t* qloG = g_qlo + (size_t)bh * T_DIM * 32;
    const uint32_t* khiG = g_khi + (size_t)bh * T_DIM * 32;
    const uint32_t* kloG = g_klo + (size_t)bh * T_DIM * 32;
    const uint32_t* vpG  = g_vp  + (size_t)bh * D_DIM * (T_DIM / 2);

    #pragma unroll
    for (int i = 0; i < 4; i++) {
        int idx = tid + i * 128;
        int r = idx >> 3, c4 = (idx & 7) * 4;
        uint4 vh = *(const uint4*)&qhiG[(size_t)(qt0 + r) * 32 + c4];
        uint4 vl = *(const uint4*)&qloG[(size_t)(qt0 + r) * 32 + c4];
        *(uint4*)&Qhi[r * QP + c4] = vh;
        *(uint4*)&Qlo[r * QP + c4] = vl;
    }

    float m0 = -1e30f, m1 = -1e30f, l0 = 0.0f, l1 = 0.0f;
    float o[8][4];
    #pragma unroll
    for (int nt = 0; nt < 8; nt++)
        #pragma unroll
        for (int r = 0; r < 4; r++) o[nt][r] = 0.0f;

    const int ra = w * 16 + grp;
    const float scale = 0.125f;

    for (int kt0 = 0; kt0 < T_DIM; kt0 += 64) {
        __syncthreads();
        #pragma unroll
        for (int i = 0; i < 4; i++) {
            int idx = tid + i * 128;
            int r = idx >> 3, c4 = (idx & 7) * 4;
            uint4 vh = *(const uint4*)&khiG[(size_t)(kt0 + r) * 32 + c4];
            uint4 vl = *(const uint4*)&kloG[(size_t)(kt0 + r) * 32 + c4];
            *(uint4*)&Khi[r * QP + c4] = vh;
            *(uint4*)&Klo[r * QP + c4] = vl;
        }
        #pragma unroll
        for (int i = 0; i < 4; i++) {
            int idx = tid + i * 128;
            int c = idx >> 3, j4 = (idx & 7) * 4;
            uint4 vv = *(const uint4*)&vpG[(size_t)c * (T_DIM / 2) + (kt0 >> 1) + j4];
            *(uint4*)&Vs[c * QP + j4] = vv;
        }
        if (tid < 64)
            Msk[tid] = (mask[b * T_DIM + kt0 + tid] == 0) ? -1e30f : 0.0f;
        __syncthreads();

        float s[8][4];
        #pragma unroll
        for (int nt = 0; nt < 8; nt++)
            #pragma unroll
            for (int r = 0; r < 4; r++) s[nt][r] = 0.0f;

        #pragma unroll
        for (int kt = 0; kt < 4; kt++) {
            int kb = kt * 8;
            int q0 = ra * QP + kb, q1 = (ra + 8) * QP + kb;
            uint32_t ah0 = Qhi[q0 + thr],     ah1 = Qhi[q1 + thr];
            uint32_t ah2 = Qhi[q0 + thr + 4], ah3 = Qhi[q1 + thr + 4];
            uint32_t al0 = Qlo[q0 + thr],     al1 = Qlo[q1 + thr];
            uint32_t al2 = Qlo[q0 + thr + 4], al3 = Qlo[q1 + thr + 4];
            #pragma unroll
            for (int nt = 0; nt < 8; nt++) {
                int c = (nt * 8 + grp) * QP + kb;
                uint32_t bh0 = Khi[c + thr], bh1 = Khi[c + thr + 4];
                uint32_t bl0 = Klo[c + thr], bl1 = Klo[c + thr + 4];
                mma_f16(s[nt][0], s[nt][1], s[nt][2], s[nt][3],
                        ah0, ah1, ah2, ah3, bh0, bh1);
                mma_f16(s[nt][0], s[nt][1], s[nt][2], s[nt][3],
                        ah0, ah1, ah2, ah3, bl0, bl1);
                mma_f16(s[nt][0], s[nt][1], s[nt][2], s[nt][3],
                        al0, al1, al2, al3, bh0, bh1);
            }
        }

        float mx0 = -1e30f, mx1 = -1e30f;
        #pragma unroll
        for (int nt = 0; nt < 8; nt++) {
            float bc0 = Msk[nt * 8 + 2 * thr];
            float bc1 = Msk[nt * 8 + 2 * thr + 1];
            s[nt][0] = fmaf(s[nt][0], scale, bc0);
            s[nt][1] = fmaf(s[nt][1], scale, bc1);
            s[nt][2] = fmaf(s[nt][2], scale, bc0);
            s[nt][3] = fmaf(s[nt][3], scale, bc1);
            mx0 = fmaxf(mx0, fmaxf(s[nt][0], s[nt][1]));
            mx1 = fmaxf(mx1, fmaxf(s[nt][2], s[nt][3]));
        }
        mx0 = fmaxf(mx0, __shfl_xor_sync(0xffffffffu, mx0, 1));
        mx0 = fmaxf(mx0, __shfl_xor_sync(0xffffffffu, mx0, 2));
        mx1 = fmaxf(mx1, __shfl_xor_sync(0xffffffffu, mx1, 1));
        mx1 = fmaxf(mx1, __shfl_xor_sync(0xffffffffu, mx1, 2));
        float mn0 = fmaxf(m0, mx0), mn1 = fmaxf(m1, mx1);
        float a0 = fast_exp(m0 - mn0), a1 = fast_exp(m1 - mn1);

        float rs0 = 0.0f, rs1 = 0.0f;
        #pragma unroll
        for (int nt = 0; nt < 8; nt++) {
            float p0 = fast_exp(s[nt][0] - mn0);
            float p1 = fast_exp(s[nt][1] - mn0);
            float p2 = fast_exp(s[nt][2] - mn1);
            float p3 = fast_exp(s[nt][3] - mn1);
            rs0 += p0 + p1;
            rs1 += p2 + p3;
            int cp = nt * 4 + thr;
            Ps[ra * QP + cp]       = pack2(p0, p1);
            Ps[(ra + 8) * QP + cp] = pack2(p2, p3);
        }
        rs0 += __shfl_xor_sync(0xffffffffu, rs0, 1);
        rs0 += __shfl_xor_sync(0xffffffffu, rs0, 2);
        rs1 += __shfl_xor_sync(0xffffffffu, rs1, 1);
        rs1 += __shfl_xor_sync(0xffffffffu, rs1, 2);
        l0 = l0 * a0 + rs0;
        l1 = l1 * a1 + rs1;
        m0 = mn0; m1 = mn1;
        #pragma unroll
        for (int nt = 0; nt < 8; nt++) {
            o[nt][0] *= a0; o[nt][1] *= a0;
            o[nt][2] *= a1; o[nt][3] *= a1;
        }
        __syncwarp();

        #pragma unroll
        for (int kt = 0; kt < 4; kt++) {
            int kb = kt * 8;
            int p0o = ra * QP + kb, p1o = (ra + 8) * QP + kb;
            uint32_t pa0 = Ps[p0o + thr],     pa1 = Ps[p1o + thr];
            uint32_t pa2 = Ps[p0o + thr + 4], pa3 = Ps[p1o + thr + 4];
            #pragma unroll
            for (int nt = 0; nt < 8; nt++) {
                int c = (nt * 8 + grp) * QP;
                uint32_t vb0 = Vs[c + kb + thr];
                uint32_t vb1 = Vs[c + kb + thr + 4];
                mma_f16(o[nt][0], o[nt][1], o[nt][2], o[nt][3],
                        pa0, pa1, pa2, pa3, vb0, vb1);
            }
        }
    }

    const int h = bh % H_DIM;
    float il0 = 1.0f / l0, il1 = 1.0f / l1;
    int t0r = qt0 + ra, t1r = qt0 + ra + 8;
    #pragma unroll
    for (int nt = 0; nt < 8; nt++) {
        int col = h * D_DIM + nt * 8 + 2 * thr;
        *(float2*)&attn_out[(size_t)(b * T_DIM + t0r) * C_DIM + col] =
            make_float2(o[nt][0] * il0, o[nt][1] * il0);
        *(float2*)&attn_out[(size_t)(b * T_DIM + t1r) * C_DIM + col] =
            make_float2(o[nt][2] * il1, o[nt][3] * il1);
    }
}

// ---------------------------------------------------------------------------
// Fused LayerNorm + residual: out = res + LN(a) * gamma + beta
// ---------------------------------------------------------------------------
__global__ void ln_residual_kernel(const float* __restrict__ res,
                                   const float* __restrict__ a,
                                   const float* __restrict__ gamma,
                                   const float* __restrict__ beta,
                                   float* __restrict__ out) {
    const int row = blockIdx.x;
    const float* ar = a + (size_t)row * C_DIM;
    const float* rr = res + (size_t)row * C_DIM;
    float* outr = out + (size_t)row * C_DIM;

    float s = 0.0f, s2 = 0.0f;
    float v[3];
    #pragma unroll
    for (int k = 0; k < 3; k++) {
        v[k] = ar[threadIdx.x + k * 256];
        s += v[k];
        s2 += v[k] * v[k];
    }
    #pragma unroll
    for (int off = 16; off >= 1; off >>= 1) {
        s  += __shfl_xor_sync(0xffffffffu, s, off);
        s2 += __shfl_xor_sync(0xffffffffu, s2, off);
    }
    __shared__ float red_s[8], red_s2[8];
    int warp = threadIdx.x >> 5, lane = threadIdx.x & 31;
    if (lane == 0) { red_s[warp] = s; red_s2[warp] = s2; }
    __syncthreads();
    if (warp == 0) {
        s  = (lane < 8) ? red_s[lane]  : 0.0f;
        s2 = (lane < 8) ? red_s2[lane] : 0.0f;
        #pragma unroll
        for (int off = 4; off >= 1; off >>= 1) {
            s  += __shfl_xor_sync(0xffffffffu, s, off);
            s2 += __shfl_xor_sync(0xffffffffu, s2, off);
        }
        if (lane == 0) { red_s[0] = s; red_s2[0] = s2; }
    }
    __syncthreads();
    const float mean = red_s[0] * (1.0f / C_DIM);
    const float var  = red_s2[0] * (1.0f / C_DIM) - mean * mean;
    const float rstd = rsqrtf(var + 1e-5f);

    #pragma unroll
    for (int k = 0; k < 3; k++) {
        int i = threadIdx.x + k * 256;
        outr[i] = rr[i] + (v[k] - mean) * rstd * gamma[i] + beta[i];
    }
}

// ---------------------------------------------------------------------------
// Launch
// ---------------------------------------------------------------------------
extern "C" void kernel_launch(void* const* d_in, const int* in_sizes, int n_in,
                              void* d_out, int out_size) {
    const float* x    = (const float*)d_in[0];
    const int*   mask = (const int*)  d_in[1];
    const float* Wqkv = (const float*)d_in[2];
    const float* bqkv = (const float*)d_in[3];
    const float* Wp   = (const float*)d_in[4];
    const float* bp   = (const float*)d_in[5];
    const float* g1   = (const float*)d_in[6];
    const float* be1  = (const float*)d_in[7];
    const float* W1   = (const float*)d_in[8];
    const float* b1   = (const float*)d_in[9];
    const float* W2   = (const float*)d_in[10];
    const float* b2   = (const float*)d_in[11];
    const float* g2   = (const float*)d_in[12];
    const float* be2  = (const float*)d_in[13];
    float* out = (float*)d_out;

    uint32_t *qhi, *qlo, *khi, *klo;
    float *vraw, *attn, *proj, *out1, *hid, *mlp;
    cudaGetSymbolAddress((void**)&qhi,  g_qhi);
    cudaGetSymbolAddress((void**)&qlo,  g_qlo);
    cudaGetSymbolAddress((void**)&khi,  g_khi);
    cudaGetSymbolAddress((void**)&klo,  g_klo);
    cudaGetSymbolAddress((void**)&vraw, g_v);
    cudaGetSymbolAddress((void**)&attn, g_attn);
    cudaGetSymbolAddress((void**)&proj, g_proj);
    cudaGetSymbolAddress((void**)&out1, g_out1);
    cudaGetSymbolAddress((void**)&hid,  g_hid);
    cudaGetSymbolAddress((void**)&mlp,  g_mlp);

    cudaFuncSetAttribute(attn_tc_kernel,
                         cudaFuncAttributeMaxDynamicSharedMemorySize,
                         FA_SMEM_BYTES);

    dim3 blk(256);

    // 1) QKV projection (epilogue writes split-fp16 Q/K + fp32 V)
    gemm_f16_kernel<2><<<dim3(QKV_N / GBN, M_ROWS / GBM), blk>>>(
        x, Wqkv, bqkv, nullptr, M_ROWS, QKV_N, C_DIM,
        qhi, qlo, khi, klo, vraw);

    // 1b) V repack into [bh][d][tp] fp16 token pairs
    repack_v_kernel<<<1536, 256>>>();

    // 2) Flash attention
    attn_tc_kernel<<<dim3(T_DIM / 64, BH), 128, FA_SMEM_BYTES>>>(mask, attn);

    // 3) Output projection
    gemm_f16_kernel<0><<<dim3(C_DIM / GBN, M_ROWS / GBM), blk>>>(
        attn, Wp, bp, proj, M_ROWS, C_DIM, C_DIM,
        nullptr, nullptr, nullptr, nullptr, nullptr);

    // 4) out1 = x + LN(proj)
    ln_residual_kernel<<<M_ROWS, blk>>>(x, proj, g1, be1, out1);

    // 5) hid = gelu(out1 @ W1 + b1)
    gemm_f16_kernel<1><<<dim3(DFF / GBN, M_ROWS / GBM), blk>>>(
        out1, W1, b1, hid, M_ROWS, DFF, C_DIM,
        nullptr, nullptr, nullptr, nullptr, nullptr);

    // 6) mlp = hid @ W2 + b2
    gemm_f16_kernel<0><<<dim3(C_DIM / GBN, M_ROWS / GBM), blk>>>(
        hid, W2, b2, mlp, M_ROWS, C_DIM, DFF,
        nullptr, nullptr, nullptr, nullptr, nullptr);

    // 7) out = out1 + LN(mlp)
    ln_residual_kernel<<<M_ROWS, blk>>>(out1, mlp, g2, be2, out);
}

// round 12
// speedup vs baseline: 6.3533x; 1.0558x over previous
#include <cuda_runtime.h>
#include <cuda_fp16.h>
#include <math.h>
#include <stdint.h>

// Problem constants
#define B_DIM 2
#define T_DIM 2048
#define C_DIM 768
#define H_DIM 12
#define D_DIM 64
#define M_ROWS (B_DIM * T_DIM)      // 4096
#define DFF (4 * C_DIM)             // 3072
#define QKV_N (3 * C_DIM)           // 2304
#define BH (B_DIM * H_DIM)          // 24

// ---------------------------------------------------------------------------
// Scratch (device globals)
// ---------------------------------------------------------------------------
__device__ uint32_t g_wqkv[(C_DIM/2) * QKV_N];     // packed weights [K/2][N]
__device__ uint32_t g_wp  [(C_DIM/2) * C_DIM];
__device__ uint32_t g_w1  [(C_DIM/2) * DFF];
__device__ uint32_t g_w2  [(DFF/2) * C_DIM];
__device__ uint32_t g_xh   [M_ROWS * (C_DIM/2)];   // packed activations [M][K/2]
__device__ uint32_t g_out1h[M_ROWS * (C_DIM/2)];
__device__ uint32_t g_attn16[M_ROWS * (C_DIM/2)];
__device__ uint32_t g_hid16 [M_ROWS * (DFF/2)];
__device__ uint32_t g_qhi[BH * T_DIM * 32];        // Q split-fp16 hi, [bh][t][d/2]
__device__ uint32_t g_qlo[BH * T_DIM * 32];
__device__ uint32_t g_khi[BH * T_DIM * 32];
__device__ uint32_t g_klo[BH * T_DIM * 32];
__device__ float    g_v  [BH * T_DIM * D_DIM];     // V fp32 [bh][t][d]
__device__ uint32_t g_vp [BH * D_DIM * (T_DIM/2)]; // V fp16 pairs [bh][d][tp]
__device__ float g_proj[M_ROWS * C_DIM];
__device__ float g_out1[M_ROWS * C_DIM];
__device__ float g_mlp [M_ROWS * C_DIM];

__device__ __forceinline__ uint32_t pack2(float a, float b) {
    __half2 h = __floats2half2_rn(a, b);
    return *(uint32_t*)&h;
}

__device__ __forceinline__ uint32_t split_pack(float a, float b, uint32_t& lo) {
    __half ha = __float2half_rn(a), hb = __float2half_rn(b);
    lo = pack2(a - __half2float(ha), b - __half2float(hb));
    __half2 h2 = __halves2half2(ha, hb);
    return *(uint32_t*)&h2;
}

__device__ __forceinline__ void mma_f16(float& d0, float& d1, float& d2, float& d3,
                                        uint32_t a0, uint32_t a1, uint32_t a2, uint32_t a3,
                                        uint32_t b0, uint32_t b1) {
    asm volatile(
        "mma.sync.aligned.m16n8k16.row.col.f32.f16.f16.f32 "
        "{%0,%1,%2,%3}, {%4,%5,%6,%7}, {%8,%9}, {%0,%1,%2,%3};\n"
        : "+f"(d0), "+f"(d1), "+f"(d2), "+f"(d3)
        : "r"(a0), "r"(a1), "r"(a2), "r"(a3), "r"(b0), "r"(b1));
}

__device__ __forceinline__ uint32_t smem_u32addr(const void* p) {
    return (uint32_t)__cvta_generic_to_shared(p);
}
__device__ __forceinline__ void cp16(uint32_t dst, const void* src) {
    asm volatile("cp.async.cg.shared.global [%0], [%1], 16;\n"
                 :: "r"(dst), "l"(src));
}

// FMA-only exp (avoids the slow MUFU pipe). |rel err| ~2.4e-6 for x <= 0.
__device__ __forceinline__ float fast_exp(float x) {
    const float LOG2E = 1.4426950408889634f;
    float y = x * LOG2E;
    y = fmaxf(y, -125.0f);
    float t = y + 12582912.0f;
    int j = __float_as_int(t);
    float r = t - 12582912.0f;
    float f = y - r;
    float p = 1.333356e-3f;
    p = fmaf(p, f, 9.618129e-3f);
    p = fmaf(p, f, 5.550411e-2f);
    p = fmaf(p, f, 2.402265e-1f);
    p = fmaf(p, f, 6.931472e-1f);
    p = fmaf(p, f, 1.0f);
    return p * __int_as_float((j + 127) << 23);
}

// ---------------------------------------------------------------------------
// Pack kernels: fp32 -> packed fp16 pairs
// ---------------------------------------------------------------------------
// W [K][N] fp32 -> out [K/2][N] u32 (pairs across adjacent k rows)
__global__ void pack_w_kernel(const float* __restrict__ W,
                              uint32_t* __restrict__ out, int K2, int N) {
    int idx = blockIdx.x * 256 + threadIdx.x;
    int n4c = N >> 2;
    if (idx >= K2 * n4c) return;
    int kp = idx / n4c;
    int n = (idx - kp * n4c) * 4;
    const float* p0 = W + (size_t)(2 * kp) * N + n;
    float4 a = *(const float4*)p0;
    float4 b = *(const float4*)(p0 + N);
    uint4 o;
    o.x = pack2(a.x, b.x); o.y = pack2(a.y, b.y);
    o.z = pack2(a.z, b.z); o.w = pack2(a.w, b.w);
    *(uint4*)&out[(size_t)kp * N + n] = o;
}

// Flat fp32 array -> packed pairs (row-contiguous; K even so rows stay aligned)
__global__ void pack_act_kernel(const float* __restrict__ in,
                                uint32_t* __restrict__ out, int n4) {
    int idx = blockIdx.x * 256 + threadIdx.x;
    if (idx >= n4) return;
    float4 v = *(const float4*)&in[(size_t)idx * 4];
    uint2 o;
    o.x = pack2(v.x, v.y);
    o.y = pack2(v.z, v.w);
    *(uint2*)&out[(size_t)idx * 2] = o;
}

// ---------------------------------------------------------------------------
// fp16 tensor-core GEMM, 4-stage cp.async pipeline, pre-packed operands.
// A [M][K/2] u32, W [K/2][N] u32. MODE: 0 = bias->fp32, 1 = bias+GELU->u32
// packed, 2 = QKV epilogue. CTA 128x128, BK=32, 256 thr, warp tile 64x32.
// ---------------------------------------------------------------------------
#define GBM 128
#define GBN 128
#define GBK 32
#define A2P 20
#define B2P 136
#define STAGES 4
#define GEMM_SMEM_U32 (STAGES * (GBM * A2P + (GBK/2) * B2P))
#define GEMM_SMEM_BYTES (GEMM_SMEM_U32 * 4)

template <int MODE>
__global__ void __launch_bounds__(256, 2)
gemm_f16_kernel(const uint32_t* __restrict__ A,
                const uint32_t* __restrict__ W,
                const float* __restrict__ bias,
                float* __restrict__ Cout,
                uint32_t* __restrict__ Cout16,
                int M, int N, int K,
                uint32_t* __restrict__ qhi, uint32_t* __restrict__ qlo,
                uint32_t* __restrict__ khi, uint32_t* __restrict__ klo,
                float* __restrict__ vout) {
    extern __shared__ uint32_t smg[];
    // As: [STAGES][GBM][A2P], Bs: [STAGES][GBK/2][B2P]
    uint32_t* Bs_base = smg + STAGES * GBM * A2P;
    const uint32_t sA_addr = smem_u32addr(smg);
    const uint32_t sB_addr = smem_u32addr(Bs_base);

    const int tid = threadIdx.x;
    const int lane = tid & 31;
    const int w = tid >> 5;
    const int warp_m = (w & 1) * 64;
    const int warp_n = (w >> 1) * 32;
    const int bm = blockIdx.y * GBM;
    const int bn = blockIdx.x * GBN;
    const int grp = lane >> 2;
    const int thr = lane & 3;
    const int K2 = K >> 1;

    // cp.async task coords (fixed)
    const int a_row0 = tid >> 2;            // chunk c = tid + i*256: row = c>>2
    const int a_seg0 = (tid & 3) * 4;
    const int b_kp0 = tid >> 5;             // row kp = c>>5
    const int b_seg0 = (tid & 31) * 4;

    auto issue_tile = [&](int ki, int st) {
        int k2 = ki * (GBK / 2);
        // A: 512 chunks of 16B (128 rows x 4 segs)
        #pragma unroll
        for (int i = 0; i < 2; i++) {
            int row = a_row0 + i * 64;
            cp16(sA_addr + (uint32_t)(((st * GBM + row) * A2P + a_seg0) * 4),
                 A + (size_t)(bm + row) * K2 + k2 + a_seg0);
        }
        // B: 512 chunks (16 kp-rows x 32 segs)
        #pragma unroll
        for (int i = 0; i < 2; i++) {
            int kp = b_kp0 + i * 8;
            cp16(sB_addr + (uint32_t)(((st * (GBK/2) + kp) * B2P + b_seg0) * 4),
                 W + (size_t)(k2 + kp) * N + bn + b_seg0);
        }
    };

    float acc[4][4][4];
    #pragma unroll
    for (int mt = 0; mt < 4; mt++)
        #pragma unroll
        for (int nt = 0; nt < 4; nt++)
            #pragma unroll
            for (int r = 0; r < 4; r++) acc[mt][nt][r] = 0.0f;

    const int nk = K / GBK;
    #pragma unroll
    for (int i = 0; i < STAGES - 1; i++) {
        issue_tile(i, i);
        asm volatile("cp.async.commit_group;\n");
    }

    for (int ki = 0; ki < nk; ki++) {
        asm volatile("cp.async.wait_group 2;\n");
        __syncthreads();
        int nx = ki + STAGES - 1;
        if (nx < nk) issue_tile(nx, nx & (STAGES - 1));
        asm volatile("cp.async.commit_group;\n");

        const int st = ki & (STAGES - 1);
        const uint32_t* Asb = smg + st * GBM * A2P;
        const uint32_t* Bsb = Bs_base + st * (GBK/2) * B2P;

        #pragma unroll
        for (int kb = 0; kb < GBK / 2; kb += 8) {
            uint32_t af[4][4], bf[4][2];
            #pragma unroll
            for (int mt = 0; mt < 4; mt++) {
                int r = warp_m + mt * 16 + grp;
                af[mt][0] = Asb[r * A2P + kb + thr];
                af[mt][1] = Asb[(r + 8) * A2P + kb + thr];
                af[mt][2] = Asb[r * A2P + kb + thr + 4];
                af[mt][3] = Asb[(r + 8) * A2P + kb + thr + 4];
            }
            #pragma unroll
            for (int nt = 0; nt < 4; nt++) {
                int c = warp_n + nt * 8 + grp;
                bf[nt][0] = Bsb[(kb + thr) * B2P + c];
                bf[nt][1] = Bsb[(kb + thr + 4) * B2P + c];
            }
            #pragma unroll
            for (int mt = 0; mt < 4; mt++)
                #pragma unroll
                for (int nt = 0; nt < 4; nt++)
                    mma_f16(acc[mt][nt][0], acc[mt][nt][1],
                            acc[mt][nt][2], acc[mt][nt][3],
                            af[mt][0], af[mt][1], af[mt][2], af[mt][3],
                            bf[nt][0], bf[nt][1]);
        }
    }

    #pragma unroll
    for (int mt = 0; mt < 4; mt++) {
        #pragma unroll
        for (int nt = 0; nt < 4; nt++) {
            int m0 = bm + warp_m + mt * 16 + grp;
            int n0 = bn + warp_n + nt * 8 + thr * 2;
            float bx = bias[n0], by = bias[n0 + 1];
            float v0 = acc[mt][nt][0] + bx;
            float v1 = acc[mt][nt][1] + by;
            float v2 = acc[mt][nt][2] + bx;
            float v3 = acc[mt][nt][3] + by;
            if (MODE == 1) {
                v0 = 0.5f * v0 * (1.0f + erff(v0 * 0.70710678118654752f));
                v1 = 0.5f * v1 * (1.0f + erff(v1 * 0.70710678118654752f));
                v2 = 0.5f * v2 * (1.0f + erff(v2 * 0.70710678118654752f));
                v3 = 0.5f * v3 * (1.0f + erff(v3 * 0.70710678118654752f));
                Cout16[(size_t)m0 * (N/2) + n0/2]       = pack2(v0, v1);
                Cout16[(size_t)(m0 + 8) * (N/2) + n0/2] = pack2(v2, v3);
            } else if (MODE == 2) {
                int bb = m0 >> 11, t = m0 & 2047;
                if (n0 < C_DIM) {
                    int h = n0 >> 6, d = n0 & 63;
                    size_t off = ((size_t)(bb * H_DIM + h) * T_DIM + t) * 32 + (d >> 1);
                    uint32_t lo, hi;
                    hi = split_pack(v0, v1, lo);
                    qhi[off] = hi; qlo[off] = lo;
                    hi = split_pack(v2, v3, lo);
                    qhi[off + 8 * 32] = hi; qlo[off + 8 * 32] = lo;
                } else if (n0 < 2 * C_DIM) {
                    int h = (n0 - C_DIM) >> 6, d = (n0 - C_DIM) & 63;
                    size_t off = ((size_t)(bb * H_DIM + h) * T_DIM + t) * 32 + (d >> 1);
                    uint32_t lo, hi;
                    hi = split_pack(v0, v1, lo);
                    khi[off] = hi; klo[off] = lo;
                    hi = split_pack(v2, v3, lo);
                    khi[off + 8 * 32] = hi; klo[off + 8 * 32] = lo;
                } else {
                    int h = (n0 - 2 * C_DIM) >> 6, d = (n0 - 2 * C_DIM) & 63;
                    size_t off = ((size_t)(bb * H_DIM + h) * T_DIM + t) * 64 + d;
                    *(float2*)&vout[off] = make_float2(v0, v1);
                    *(float2*)&vout[off + 8 * 64] = make_float2(v2, v3);
                }
            } else {
                *(float2*)&Cout[(size_t)m0 * N + n0] = make_float2(v0, v1);
                *(float2*)&Cout[(size_t)(m0 + 8) * N + n0] = make_float2(v2, v3);
            }
        }
    }
}

// ---------------------------------------------------------------------------
// V repack: g_v [bh][t][d] fp32 -> g_vp [bh][d][tp] u32 (fp16 token pairs).
// ---------------------------------------------------------------------------
__global__ void repack_v_kernel() {
    int o = blockIdx.x * 256 + threadIdx.x;
    int tp0 = (o & 255) * 4;
    int row = o >> 8;
    const float* src = g_v + (size_t)(row >> 6) * T_DIM * D_DIM + (row & 63);
    uint32_t out[4];
    #pragma unroll
    for (int j = 0; j < 4; j++) {
        int t0 = (tp0 + j) * 2;
        out[j] = pack2(src[(size_t)t0 * D_DIM], src[(size_t)(t0 + 1) * D_DIM]);
    }
    *(uint4*)&g_vp[(size_t)row * (T_DIM / 2) + tp0] = *(uint4*)out;
}

// ---------------------------------------------------------------------------
// fp16 tensor-core flash attention (epilogue now writes packed fp16).
// ---------------------------------------------------------------------------
#define QP 36
#define FA_U32S (6 * 64 * QP + 64)
#define FA_SMEM_BYTES (FA_U32S * 4)

__global__ void __launch_bounds__(128, 4)
attn_tc_kernel(const int* __restrict__ mask, uint32_t* __restrict__ attn16) {
    extern __shared__ uint32_t sm[];
    uint32_t* Qhi = sm;
    uint32_t* Qlo = Qhi + 64 * QP;
    uint32_t* Khi = Qlo + 64 * QP;
    uint32_t* Klo = Khi + 64 * QP;
    uint32_t* Ps  = Klo + 64 * QP;
    uint32_t* Vs  = Ps  + 64 * QP;
    float*    Msk = (float*)(Vs + 64 * QP);

    const int tid = threadIdx.x;
    const int lane = tid & 31;
    const int w = tid >> 5;
    const int grp = lane >> 2;
    const int thr = lane & 3;
    const int bh = blockIdx.y;
    const int b = bh / H_DIM;
    const int qt0 = blockIdx.x * 64;

    const uint32_t* qhiG = g_qhi + (size_t)bh * T_DIM * 32;
    const uint32_t* qloG = g_qlo + (size_t)bh * T_DIM * 32;
    const uint32_t* khiG = g_khi + (size_t)bh * T_DIM * 32;
    const uint32_t* kloG = g_klo + (size_t)bh * T_DIM * 32;
    const uint32_t* vpG  = g_vp  + (size_t)bh * D_DIM * (T_DIM / 2);

    #pragma unroll
    for (int i = 0; i < 4; i++) {
        int idx = tid + i * 128;
        int r = idx >> 3, c4 = (idx & 7) * 4;
        uint4 vh = *(const uint4*)&qhiG[(size_t)(qt0 + r) * 32 + c4];
        uint4 vl = *(const uint4*)&qloG[(size_t)(qt0 + r) * 32 + c4];
        *(uint4*)&Qhi[r * QP + c4] = vh;
        *(uint4*)&Qlo[r * QP + c4] = vl;
    }

    float m0 = -1e30f, m1 = -1e30f, l0 = 0.0f, l1 = 0.0f;
    float o[8][4];
    #pragma unroll
    for (int nt = 0; nt < 8; nt++)
        #pragma unroll
        for (int r = 0; r < 4; r++) o[nt][r] = 0.0f;

    const int ra = w * 16 + grp;
    const float scale = 0.125f;

    for (int kt0 = 0; kt0 < T_DIM; kt0 += 64) {
        __syncthreads();
        #pragma unroll
        for (int i = 0; i < 4; i++) {
            int idx = tid + i * 128;
            int r = idx >> 3, c4 = (idx & 7) * 4;
            uint4 vh = *(const uint4*)&khiG[(size_t)(kt0 + r) * 32 + c4];
            uint4 vl = *(const uint4*)&kloG[(size_t)(kt0 + r) * 32 + c4];
            *(uint4*)&Khi[r * QP + c4] = vh;
            *(uint4*)&Klo[r * QP + c4] = vl;
        }
        #pragma unroll
        for (int i = 0; i < 4; i++) {
            int idx = tid + i * 128;
            int c = idx >> 3, j4 = (idx & 7) * 4;
            uint4 vv = *(const uint4*)&vpG[(size_t)c * (T_DIM / 2) + (kt0 >> 1) + j4];
            *(uint4*)&Vs[c * QP + j4] = vv;
        }
        if (tid < 64)
            Msk[tid] = (mask[b * T_DIM + kt0 + tid] == 0) ? -1e30f : 0.0f;
        __syncthreads();

        float s[8][4];
        #pragma unroll
        for (int nt = 0; nt < 8; nt++)
            #pragma unroll
            for (int r = 0; r < 4; r++) s[nt][r] = 0.0f;

        #pragma unroll
        for (int kt = 0; kt < 4; kt++) {
            int kb = kt * 8;
            int q0 = ra * QP + kb, q1 = (ra + 8) * QP + kb;
            uint32_t ah0 = Qhi[q0 + thr],     ah1 = Qhi[q1 + thr];
            uint32_t ah2 = Qhi[q0 + thr + 4], ah3 = Qhi[q1 + thr + 4];
            uint32_t al0 = Qlo[q0 + thr],     al1 = Qlo[q1 + thr];
            uint32_t al2 = Qlo[q0 + thr + 4], al3 = Qlo[q1 + thr + 4];
            #pragma unroll
            for (int nt = 0; nt < 8; nt++) {
                int c = (nt * 8 + grp) * QP + kb;
                uint32_t bh0 = Khi[c + thr], bh1 = Khi[c + thr + 4];
                uint32_t bl0 = Klo[c + thr], bl1 = Klo[c + thr + 4];
                mma_f16(s[nt][0], s[nt][1], s[nt][2], s[nt][3],
                        ah0, ah1, ah2, ah3, bh0, bh1);
                mma_f16(s[nt][0], s[nt][1], s[nt][2], s[nt][3],
                        ah0, ah1, ah2, ah3, bl0, bl1);
                mma_f16(s[nt][0], s[nt][1], s[nt][2], s[nt][3],
                        al0, al1, al2, al3, bh0, bh1);
            }
        }

        float mx0 = -1e30f, mx1 = -1e30f;
        #pragma unroll
        for (int nt = 0; nt < 8; nt++) {
            float bc0 = Msk[nt * 8 + 2 * thr];
            float bc1 = Msk[nt * 8 + 2 * thr + 1];
            s[nt][0] = fmaf(s[nt][0], scale, bc0);
            s[nt][1] = fmaf(s[nt][1], scale, bc1);
            s[nt][2] = fmaf(s[nt][2], scale, bc0);
            s[nt][3] = fmaf(s[nt][3], scale, bc1);
            mx0 = fmaxf(mx0, fmaxf(s[nt][0], s[nt][1]));
            mx1 = fmaxf(mx1, fmaxf(s[nt][2], s[nt][3]));
        }
        mx0 = fmaxf(mx0, __shfl_xor_sync(0xffffffffu, mx0, 1));
        mx0 = fmaxf(mx0, __shfl_xor_sync(0xffffffffu, mx0, 2));
        mx1 = fmaxf(mx1, __shfl_xor_sync(0xffffffffu, mx1, 1));
        mx1 = fmaxf(mx1, __shfl_xor_sync(0xffffffffu, mx1, 2));
        float mn0 = fmaxf(m0, mx0), mn1 = fmaxf(m1, mx1);
        float a0 = fast_exp(m0 - mn0), a1 = fast_exp(m1 - mn1);

        float rs0 = 0.0f, rs1 = 0.0f;
        #pragma unroll
        for (int nt = 0; nt < 8; nt++) {
            float p0 = fast_exp(s[nt][0] - mn0);
            float p1 = fast_exp(s[nt][1] - mn0);
            float p2 = fast_exp(s[nt][2] - mn1);
            float p3 = fast_exp(s[nt][3] - mn1);
            rs0 += p0 + p1;
            rs1 += p2 + p3;
            int cp = nt * 4 + thr;
            Ps[ra * QP + cp]       = pack2(p0, p1);
            Ps[(ra + 8) * QP + cp] = pack2(p2, p3);
        }
        rs0 += __shfl_xor_sync(0xffffffffu, rs0, 1);
        rs0 += __shfl_xor_sync(0xffffffffu, rs0, 2);
        rs1 += __shfl_xor_sync(0xffffffffu, rs1, 1);
        rs1 += __shfl_xor_sync(0xffffffffu, rs1, 2);
        l0 = l0 * a0 + rs0;
        l1 = l1 * a1 + rs1;
        m0 = mn0; m1 = mn1;
        #pragma unroll
        for (int nt = 0; nt < 8; nt++) {
            o[nt][0] *= a0; o[nt][1] *= a0;
            o[nt][2] *= a1; o[nt][3] *= a1;
        }
        __syncwarp();

        #pragma unroll
        for (int kt = 0; kt < 4; kt++) {
            int kb = kt * 8;
            int p0o = ra * QP + kb, p1o = (ra + 8) * QP + kb;
            uint32_t pa0 = Ps[p0o + thr],     pa1 = Ps[p1o + thr];
            uint32_t pa2 = Ps[p0o + thr + 4], pa3 = Ps[p1o + thr + 4];
            #pragma unroll
            for (int nt = 0; nt < 8; nt++) {
                int c = (nt * 8 + grp) * QP;
                uint32_t vb0 = Vs[c + kb + thr];
                uint32_t vb1 = Vs[c + kb + thr + 4];
                mma_f16(o[nt][0], o[nt][1], o[nt][2], o[nt][3],
                        pa0, pa1, pa2, pa3, vb0, vb1);
            }
        }
    }

    // Write packed fp16 output, ready to be proj's A operand
    const int h = bh % H_DIM;
    float il0 = 1.0f / l0, il1 = 1.0f / l1;
    int t0r = qt0 + ra, t1r = qt0 + ra + 8;
    #pragma unroll
    for (int nt = 0; nt < 8; nt++) {
        int cp = h * 32 + nt * 4 + thr;
        attn16[(size_t)(b * T_DIM + t0r) * (C_DIM/2) + cp] =
            pack2(o[nt][0] * il0, o[nt][1] * il0);
        attn16[(size_t)(b * T_DIM + t1r) * (C_DIM/2) + cp] =
            pack2(o[nt][2] * il1, o[nt][3] * il1);
    }
}

// ---------------------------------------------------------------------------
// Fused LayerNorm + residual: out = res + LN(a) * gamma + beta
// ---------------------------------------------------------------------------
__global__ void ln_residual_kernel(const float* __restrict__ res,
                                   const float* __restrict__ a,
                                   const float* __restrict__ gamma,
                                   const float* __restrict__ beta,
                                   float* __restrict__ out) {
    const int row = blockIdx.x;
    const float* ar = a + (size_t)row * C_DIM;
    const float* rr = res + (size_t)row * C_DIM;
    float* outr = out + (size_t)row * C_DIM;

    float s = 0.0f, s2 = 0.0f;
    float v[3];
    #pragma unroll
    for (int k = 0; k < 3; k++) {
        v[k] = ar[threadIdx.x + k * 256];
        s += v[k];
        s2 += v[k] * v[k];
    }
    #pragma unroll
    for (int off = 16; off >= 1; off >>= 1) {
        s  += __shfl_xor_sync(0xffffffffu, s, off);
        s2 += __shfl_xor_sync(0xffffffffu, s2, off);
    }
    __shared__ float red_s[8], red_s2[8];
    int warp = threadIdx.x >> 5, lane = threadIdx.x & 31;
    if (lane == 0) { red_s[warp] = s; red_s2[warp] = s2; }
    __syncthreads();
    if (warp == 0) {
        s  = (lane < 8) ? red_s[lane]  : 0.0f;
        s2 = (lane < 8) ? red_s2[lane] : 0.0f;
        #pragma unroll
        for (int off = 4; off >= 1; off >>= 1) {
            s  += __shfl_xor_sync(0xffffffffu, s, off);
            s2 += __shfl_xor_sync(0xffffffffu, s2, off);
        }
        if (lane == 0) { red_s[0] = s; red_s2[0] = s2; }
    }
    __syncthreads();
    const float mean = red_s[0] * (1.0f / C_DIM);
    const float var  = red_s2[0] * (1.0f / C_DIM) - mean * mean;
    const float rstd = rsqrtf(var + 1e-5f);

    #pragma unroll
    for (int k = 0; k < 3; k++) {
        int i = threadIdx.x + k * 256;
        outr[i] = rr[i] + (v[k] - mean) * rstd * gamma[i] + beta[i];
    }
}

// ---------------------------------------------------------------------------
// Launch
// ---------------------------------------------------------------------------
extern "C" void kernel_launch(void* const* d_in, const int* in_sizes, int n_in,
                              void* d_out, int out_size) {
    const float* x    = (const float*)d_in[0];
    const int*   mask = (const int*)  d_in[1];
    const float* Wqkv = (const float*)d_in[2];
    const float* bqkv = (const float*)d_in[3];
    const float* Wp   = (const float*)d_in[4];
    const float* bp   = (const float*)d_in[5];
    const float* g1   = (const float*)d_in[6];
    const float* be1  = (const float*)d_in[7];
    const float* W1   = (const float*)d_in[8];
    const float* b1   = (const float*)d_in[9];
    const float* W2   = (const float*)d_in[10];
    const float* b2   = (const float*)d_in[11];
    const float* g2   = (const float*)d_in[12];
    const float* be2  = (const float*)d_in[13];
    float* out = (float*)d_out;

    uint32_t *wqkv, *wp, *w1, *w2, *xh, *out1h, *attn16, *hid16;
    uint32_t *qhi, *qlo, *khi, *klo;
    float *vraw, *proj, *out1, *mlp;
    cudaGetSymbolAddress((void**)&wqkv,   g_wqkv);
    cudaGetSymbolAddress((void**)&wp,     g_wp);
    cudaGetSymbolAddress((void**)&w1,     g_w1);
    cudaGetSymbolAddress((void**)&w2,     g_w2);
    cudaGetSymbolAddress((void**)&xh,     g_xh);
    cudaGetSymbolAddress((void**)&out1h,  g_out1h);
    cudaGetSymbolAddress((void**)&attn16, g_attn16);
    cudaGetSymbolAddress((void**)&hid16,  g_hid16);
    cudaGetSymbolAddress((void**)&qhi,  g_qhi);
    cudaGetSymbolAddress((void**)&qlo,  g_qlo);
    cudaGetSymbolAddress((void**)&khi,  g_khi);
    cudaGetSymbolAddress((void**)&klo,  g_klo);
    cudaGetSymbolAddress((void**)&vraw, g_v);
    cudaGetSymbolAddress((void**)&proj, g_proj);
    cudaGetSymbolAddress((void**)&out1, g_out1);
    cudaGetSymbolAddress((void**)&mlp,  g_mlp);

    cudaFuncSetAttribute(attn_tc_kernel,
                         cudaFuncAttributeMaxDynamicSharedMemorySize,
                         FA_SMEM_BYTES);
    cudaFuncSetAttribute(gemm_f16_kernel<0>,
                         cudaFuncAttributeMaxDynamicSharedMemorySize,
                         GEMM_SMEM_BYTES);
    cudaFuncSetAttribute(gemm_f16_kernel<1>,
                         cudaFuncAttributeMaxDynamicSharedMemorySize,
                         GEMM_SMEM_BYTES);
    cudaFuncSetAttribute(gemm_f16_kernel<2>,
                         cudaFuncAttributeMaxDynamicSharedMemorySize,
                         GEMM_SMEM_BYTES);

    dim3 blk(256);

    // 0) Pack weights and input activations to fp16 pairs
    pack_w_kernel<<<(384 * (QKV_N/4) + 255) / 256, blk>>>(Wqkv, wqkv, 384, QKV_N);
    pack_w_kernel<<<(384 * (C_DIM/4) + 255) / 256, blk>>>(Wp, wp, 384, C_DIM);
    pack_w_kernel<<<(384 * (DFF/4) + 255) / 256, blk>>>(W1, w1, 384, DFF);
    pack_w_kernel<<<(1536 * (C_DIM/4) + 255) / 256, blk>>>(W2, w2, 1536, C_DIM);
    pack_act_kernel<<<(M_ROWS * C_DIM / 4 + 255) / 256, blk>>>(x, xh, M_ROWS * C_DIM / 4);

    // 1) QKV projection (epilogue writes split-fp16 Q/K + fp32 V)
    gemm_f16_kernel<2><<<dim3(QKV_N / GBN, M_ROWS / GBM), blk, GEMM_SMEM_BYTES>>>(
        xh, wqkv, bqkv, nullptr, nullptr, M_ROWS, QKV_N, C_DIM,
        qhi, qlo, khi, klo, vraw);

    // 1b) V repack into [bh][d][tp] fp16 token pairs
    repack_v_kernel<<<1536, 256>>>();

    // 2) Flash attention -> packed fp16
    attn_tc_kernel<<<dim3(T_DIM / 64, BH), 128, FA_SMEM_BYTES>>>(mask, attn16);

    // 3) Output projection
    gemm_f16_kernel<0><<<dim3(C_DIM / GBN, M_ROWS / GBM), blk, GEMM_SMEM_BYTES>>>(
        attn16, wp, bp, proj, nullptr, M_ROWS, C_DIM, C_DIM,
        nullptr, nullptr, nullptr, nullptr, nullptr);

    // 4) out1 = x + LN(proj); pack for mlp1
    ln_residual_kernel<<<M_ROWS, blk>>>(x, proj, g1, be1, out1);
    pack_act_kernel<<<(M_ROWS * C_DIM / 4 + 255) / 256, blk>>>(out1, out1h, M_ROWS * C_DIM / 4);

    // 5) hid = gelu(out1 @ W1 + b1) -> packed fp16
    gemm_f16_kernel<1><<<dim3(DFF / GBN, M_ROWS / GBM), blk, GEMM_SMEM_BYTES>>>(
        out1h, w1, b1, nullptr, hid16, M_ROWS, DFF, C_DIM,
        nullptr, nullptr, nullptr, nullptr, nullptr);

    // 6) mlp = hid @ W2 + b2
    gemm_f16_kernel<0><<<dim3(C_DIM / GBN, M_ROWS / GBM), blk, GEMM_SMEM_BYTES>>>(
        hid16, w2, b2, mlp, nullptr, M_ROWS, C_DIM, DFF,
        nullptr, nullptr, nullptr, nullptr, nullptr);

    // 7) out = out1 + LN(mlp)
    ln_residual_kernel<<<M_ROWS, blk>>>(out1, mlp, g2, be2, out);
}